// round 2
// baseline (speedup 1.0000x reference)
#include <cuda_runtime.h>
#include <math.h>

#define NN 10000
#define EE 160000
#define DD 128
#define QB 157            // ceil(NN/64)
#define KSPLIT 8
#define CHUNK (NN / KSPLIT)   // 1250

// ---------------- scratch (static device arrays; no cudaMalloc) ------------
__device__ float g_agg1[NN*DD];
__device__ float g_agg2[NN*DD];
__device__ float g_h[NN*DD];
__device__ float g_embed[NN*DD];
__device__ float g_Q[NN*DD];
__device__ float g_K[NN*DD];
__device__ float g_V[NN*DD];
__device__ float g_gb[3*DD];          // fused (node bias + global projection) per Q/K/V
__device__ float g_attnsum[DD];       // sum over all output rows of attention
__device__ float g_pm[QB*KSPLIT*64];
__device__ float g_pl[QB*KSPLIT*64];
__device__ float g_pacc[QB*KSPLIT*64*DD];   // ~41 MB partial accumulators

// ---------------- zero scratch --------------------------------------------
__global__ void zero_kernel() {
    int t = blockIdx.x * blockDim.x + threadIdx.x;
    if (t < NN*DD) { g_agg1[t] = 0.f; g_agg2[t] = 0.f; }
    if (t < DD) g_attnsum[t] = 0.f;
}

// ---------------- scatter-add: agg[dst] += x[src] --------------------------
__global__ __launch_bounds__(256) void scatter_kernel(
        const float* __restrict__ x, const int* __restrict__ src,
        const int* __restrict__ dst, float* __restrict__ agg) {
    int t = blockIdx.x * 256 + threadIdx.x;
    int e = t >> 5;
    if (e >= EE) return;
    int fq = (t & 31) << 2;
    int s = __ldg(src + e);
    int d = __ldg(dst + e);
    float4 v = *reinterpret_cast<const float4*>(x + (size_t)s * DD + fq);
    float* p = agg + (size_t)d * DD + fq;
    atomicAdd(p + 0, v.x); atomicAdd(p + 1, v.y);
    atomicAdd(p + 2, v.z); atomicAdd(p + 3, v.w);
}

// ---------------- fused dual GEMM: out = [X|Y] @ [Wa;Wb] + b (opt. relu) ---
// CTA: 256 threads, 32 rows. smem: W 256x128 (128KB) + A 32x256 (32KB)
#define CONV_SMEM ((256*128 + 32*256) * 4)
template<bool RELU>
__global__ __launch_bounds__(256) void conv_kernel(
        const float* __restrict__ X, const float* __restrict__ Y,
        const float* __restrict__ Wa, const float* __restrict__ Wb,
        const float* __restrict__ bias, float* __restrict__ out) {
    extern __shared__ float sm[];
    float* sW = sm;             // [256][128]
    float* sA = sm + 256*128;   // [32][256]
    int tid = threadIdx.x;
    int row0 = blockIdx.x * 32;

    for (int i = tid*4; i < 256*128; i += 1024) {
        float4 v;
        if (i < 128*128) v = *reinterpret_cast<const float4*>(Wa + i);
        else             v = *reinterpret_cast<const float4*>(Wb + (i - 128*128));
        *reinterpret_cast<float4*>(sW + i) = v;
    }
    for (int i = tid*4; i < 32*256; i += 1024) {
        int r = i >> 8, c = i & 255;
        int gr = row0 + r;
        float4 v = make_float4(0.f,0.f,0.f,0.f);
        if (gr < NN) {
            if (c < 128) v = *reinterpret_cast<const float4*>(X + (size_t)gr*128 + c);
            else         v = *reinterpret_cast<const float4*>(Y + (size_t)gr*128 + (c-128));
        }
        *reinterpret_cast<float4*>(sA + i) = v;
    }
    __syncthreads();

    int w = tid >> 5, lane = tid & 31;
    int r0 = w * 4;
    float4 bb = *reinterpret_cast<const float4*>(bias + lane*4);
    float acc[4][4];
    #pragma unroll
    for (int i = 0; i < 4; i++) { acc[i][0]=bb.x; acc[i][1]=bb.y; acc[i][2]=bb.z; acc[i][3]=bb.w; }

    for (int k = 0; k < 256; k += 4) {
        float a0[4], a1[4], a2[4], a3[4];
        #pragma unroll
        for (int i = 0; i < 4; i++) {
            float4 t = *reinterpret_cast<const float4*>(sA + (r0+i)*256 + k);
            a0[i]=t.x; a1[i]=t.y; a2[i]=t.z; a3[i]=t.w;
        }
        float4 b;
        b = *reinterpret_cast<const float4*>(sW + (k+0)*128 + lane*4);
        #pragma unroll
        for (int i=0;i<4;i++){ acc[i][0]+=a0[i]*b.x; acc[i][1]+=a0[i]*b.y; acc[i][2]+=a0[i]*b.z; acc[i][3]+=a0[i]*b.w; }
        b = *reinterpret_cast<const float4*>(sW + (k+1)*128 + lane*4);
        #pragma unroll
        for (int i=0;i<4;i++){ acc[i][0]+=a1[i]*b.x; acc[i][1]+=a1[i]*b.y; acc[i][2]+=a1[i]*b.z; acc[i][3]+=a1[i]*b.w; }
        b = *reinterpret_cast<const float4*>(sW + (k+2)*128 + lane*4);
        #pragma unroll
        for (int i=0;i<4;i++){ acc[i][0]+=a2[i]*b.x; acc[i][1]+=a2[i]*b.y; acc[i][2]+=a2[i]*b.z; acc[i][3]+=a2[i]*b.w; }
        b = *reinterpret_cast<const float4*>(sW + (k+3)*128 + lane*4);
        #pragma unroll
        for (int i=0;i<4;i++){ acc[i][0]+=a3[i]*b.x; acc[i][1]+=a3[i]*b.y; acc[i][2]+=a3[i]*b.z; acc[i][3]+=a3[i]*b.w; }
    }

    #pragma unroll
    for (int i = 0; i < 4; i++) {
        int gr = row0 + r0 + i;
        if (gr < NN) {
            float4 o;
            if (RELU) { o.x=fmaxf(acc[i][0],0.f); o.y=fmaxf(acc[i][1],0.f); o.z=fmaxf(acc[i][2],0.f); o.w=fmaxf(acc[i][3],0.f); }
            else      { o.x=acc[i][0]; o.y=acc[i][1]; o.z=acc[i][2]; o.w=acc[i][3]; }
            *reinterpret_cast<float4*>(out + (size_t)gr*128 + lane*4) = o;
        }
    }
}

// ---------------- global-bias precompute -----------------------------------
__global__ void gbias_kernel(const float* __restrict__ g,
        const float* __restrict__ WQg, const float* __restrict__ bQg,
        const float* __restrict__ WKg, const float* __restrict__ bKg,
        const float* __restrict__ WVg, const float* __restrict__ bVg,
        const float* __restrict__ bQ, const float* __restrict__ bK,
        const float* __restrict__ bV) {
    int t = threadIdx.x;            // 384 threads
    int m = t >> 7, f = t & 127;
    const float* Wg = (m == 0) ? WQg : ((m == 1) ? WKg : WVg);
    const float* bg = (m == 0) ? bQg : ((m == 1) ? bKg : bVg);
    const float* bn = (m == 0) ? bQ  : ((m == 1) ? bK  : bV);
    float s = bg[f] + bn[f];
    for (int d = 0; d < 64; d++) s += g[d] * Wg[d*128 + f];
    g_gb[t] = s;
}

// ---------------- QKV: [Q|K|V] = embed @ [WQ|WK|WV] + g_gb ----------------
#define QKV_SMEM ((128*384 + 32*128) * 4)
__global__ __launch_bounds__(256) void qkv_kernel(
        const float* __restrict__ WQ, const float* __restrict__ WK,
        const float* __restrict__ WV) {
    extern __shared__ float sm[];
    float* sW = sm;              // [128][384]
    float* sA = sm + 128*384;    // [32][128]
    int tid = threadIdx.x;
    int row0 = blockIdx.x * 32;

    for (int i = tid*4; i < 128*384; i += 1024) {
        int k = i / 384, c = i % 384;
        int m = c >> 7, cc = c & 127;
        const float* W = (m == 0) ? WQ : ((m == 1) ? WK : WV);
        *reinterpret_cast<float4*>(sW + i) =
            *reinterpret_cast<const float4*>(W + k*128 + cc);
    }
    for (int i = tid*4; i < 32*128; i += 1024) {
        int r = i >> 7, c = i & 127;
        int gr = row0 + r;
        float4 v = make_float4(0.f,0.f,0.f,0.f);
        if (gr < NN) v = *reinterpret_cast<const float4*>(g_embed + (size_t)gr*128 + c);
        *reinterpret_cast<float4*>(sA + i) = v;
    }
    __syncthreads();

    int w = tid >> 5, lane = tid & 31;
    int r0 = w * 4;
    float acc[4][12];
    {
        float4 q0 = *reinterpret_cast<const float4*>(g_gb + 0*128 + lane*4);
        float4 q1 = *reinterpret_cast<const float4*>(g_gb + 1*128 + lane*4);
        float4 q2 = *reinterpret_cast<const float4*>(g_gb + 2*128 + lane*4);
        #pragma unroll
        for (int i = 0; i < 4; i++) {
            acc[i][0]=q0.x; acc[i][1]=q0.y; acc[i][2]=q0.z; acc[i][3]=q0.w;
            acc[i][4]=q1.x; acc[i][5]=q1.y; acc[i][6]=q1.z; acc[i][7]=q1.w;
            acc[i][8]=q2.x; acc[i][9]=q2.y; acc[i][10]=q2.z; acc[i][11]=q2.w;
        }
    }
    for (int k = 0; k < 128; k++) {
        float4 b0 = *reinterpret_cast<const float4*>(sW + k*384 +   0 + lane*4);
        float4 b1 = *reinterpret_cast<const float4*>(sW + k*384 + 128 + lane*4);
        float4 b2 = *reinterpret_cast<const float4*>(sW + k*384 + 256 + lane*4);
        #pragma unroll
        for (int i = 0; i < 4; i++) {
            float a = sA[(r0+i)*128 + k];
            acc[i][0]+=a*b0.x; acc[i][1]+=a*b0.y; acc[i][2]+=a*b0.z;  acc[i][3]+=a*b0.w;
            acc[i][4]+=a*b1.x; acc[i][5]+=a*b1.y; acc[i][6]+=a*b1.z;  acc[i][7]+=a*b1.w;
            acc[i][8]+=a*b2.x; acc[i][9]+=a*b2.y; acc[i][10]+=a*b2.z; acc[i][11]+=a*b2.w;
        }
    }
    #pragma unroll
    for (int i = 0; i < 4; i++) {
        int gr = row0 + r0 + i;
        if (gr < NN) {
            *reinterpret_cast<float4*>(g_Q + (size_t)gr*128 + lane*4) = make_float4(acc[i][0],acc[i][1],acc[i][2],acc[i][3]);
            *reinterpret_cast<float4*>(g_K + (size_t)gr*128 + lane*4) = make_float4(acc[i][4],acc[i][5],acc[i][6],acc[i][7]);
            *reinterpret_cast<float4*>(g_V + (size_t)gr*128 + lane*4) = make_float4(acc[i][8],acc[i][9],acc[i][10],acc[i][11]);
        }
    }
}

// ---------------- flash attention (split-K partials) -----------------------
// BQ=64, BK=64, 256 threads. Thread (ty,tx): rows ty+16i, S-cols tx+16j,
// PV-cols 4tx+64u+v. Stride 132 (Q/K/V) and 66 (P) -> conflict-free phases.
#define ATTN_SMEM ((3*64*132 + 64*66) * 4)
__global__ __launch_bounds__(256) void attn_kernel() {
    extern __shared__ float sm[];
    float* sQ = sm;                // [64][132]
    float* sK = sQ + 64*132;
    float* sV = sK + 64*132;
    float* sP = sV + 64*132;       // [64][66]
    const int tid = threadIdx.x;
    const int qb = blockIdx.x;
    const int chunk = blockIdx.y;
    const int qrow0 = qb * 64;
    const int kbeg = chunk * CHUNK;
    const int kend = kbeg + CHUNK;

    for (int i = tid*4; i < 64*128; i += 1024) {
        int r = i >> 7, c = i & 127;
        int gr = qrow0 + r;
        float4 v = make_float4(0.f,0.f,0.f,0.f);
        if (gr < NN) v = *reinterpret_cast<const float4*>(g_Q + (size_t)gr*128 + c);
        *reinterpret_cast<float4*>(sQ + r*132 + c) = v;
    }

    const int ty = tid >> 4;   // 0..15
    const int tx = tid & 15;   // 0..15
    float m_i[4], l_i[4], acc[4][8];
    #pragma unroll
    for (int i = 0; i < 4; i++) {
        m_i[i] = -1e30f; l_i[i] = 0.f;
        #pragma unroll
        for (int j = 0; j < 8; j++) acc[i][j] = 0.f;
    }
    const float scale = 0.088388347648318447f;   // 1/sqrt(128)

    for (int kt = kbeg; kt < kend; kt += 64) {
        const int kn = min(64, kend - kt);
        __syncthreads();   // prior PV reads done before overwriting K/V/P
        for (int i = tid*4; i < 64*128; i += 1024) {
            int r = i >> 7, c = i & 127;
            float4 kv = make_float4(0.f,0.f,0.f,0.f);
            float4 vv = make_float4(0.f,0.f,0.f,0.f);
            if (r < kn) {
                kv = *reinterpret_cast<const float4*>(g_K + (size_t)(kt+r)*128 + c);
                vv = *reinterpret_cast<const float4*>(g_V + (size_t)(kt+r)*128 + c);
            }
            *reinterpret_cast<float4*>(sK + r*132 + c) = kv;
            *reinterpret_cast<float4*>(sV + r*132 + c) = vv;
        }
        __syncthreads();

        // ---- S = Q K^T (4x4 per thread) ----
        float s[4][4];
        #pragma unroll
        for (int i = 0; i < 4; i++)
            #pragma unroll
            for (int j = 0; j < 4; j++) s[i][j] = 0.f;

        for (int k = 0; k < 128; k += 4) {
            float4 qv[4], kv[4];
            #pragma unroll
            for (int i = 0; i < 4; i++)
                qv[i] = *reinterpret_cast<const float4*>(sQ + (ty+16*i)*132 + k);
            #pragma unroll
            for (int j = 0; j < 4; j++)
                kv[j] = *reinterpret_cast<const float4*>(sK + (tx+16*j)*132 + k);
            #pragma unroll
            for (int i = 0; i < 4; i++)
                #pragma unroll
                for (int j = 0; j < 4; j++)
                    s[i][j] += qv[i].x*kv[j].x + qv[i].y*kv[j].y
                             + qv[i].z*kv[j].z + qv[i].w*kv[j].w;
        }
        #pragma unroll
        for (int j = 0; j < 4; j++) {
            bool valid = (tx + 16*j) < kn;
            #pragma unroll
            for (int i = 0; i < 4; i++)
                s[i][j] = valid ? s[i][j] * scale : -1e30f;
        }

        // ---- online softmax update per row ----
        #pragma unroll
        for (int i = 0; i < 4; i++) {
            float rm = fmaxf(fmaxf(s[i][0], s[i][1]), fmaxf(s[i][2], s[i][3]));
            rm = fmaxf(rm, __shfl_xor_sync(0xffffffffu, rm, 1));
            rm = fmaxf(rm, __shfl_xor_sync(0xffffffffu, rm, 2));
            rm = fmaxf(rm, __shfl_xor_sync(0xffffffffu, rm, 4));
            rm = fmaxf(rm, __shfl_xor_sync(0xffffffffu, rm, 8));
            float mnew = fmaxf(m_i[i], rm);
            float sc = expf(m_i[i] - mnew);
            float p0 = expf(s[i][0] - mnew);
            float p1 = expf(s[i][1] - mnew);
            float p2 = expf(s[i][2] - mnew);
            float p3 = expf(s[i][3] - mnew);
            float rs = p0 + p1 + p2 + p3;
            rs += __shfl_xor_sync(0xffffffffu, rs, 1);
            rs += __shfl_xor_sync(0xffffffffu, rs, 2);
            rs += __shfl_xor_sync(0xffffffffu, rs, 4);
            rs += __shfl_xor_sync(0xffffffffu, rs, 8);
            l_i[i] = l_i[i] * sc + rs;
            m_i[i] = mnew;
            #pragma unroll
            for (int j = 0; j < 8; j++) acc[i][j] *= sc;
            float* pr = sP + (ty + 16*i) * 66;
            pr[tx     ] = p0;
            pr[tx + 16] = p1;
            pr[tx + 32] = p2;
            pr[tx + 48] = p3;
        }
        __syncthreads();

        // ---- acc += P @ V ----
        for (int k2 = 0; k2 < 64; k2++) {
            float4 v0 = *reinterpret_cast<const float4*>(sV + k2*132 + 4*tx);
            float4 v1 = *reinterpret_cast<const float4*>(sV + k2*132 + 4*tx + 64);
            #pragma unroll
            for (int i = 0; i < 4; i++) {
                float p = sP[(ty + 16*i)*66 + k2];
                acc[i][0] += p*v0.x; acc[i][1] += p*v0.y;
                acc[i][2] += p*v0.z; acc[i][3] += p*v0.w;
                acc[i][4] += p*v1.x; acc[i][5] += p*v1.y;
                acc[i][6] += p*v1.z; acc[i][7] += p*v1.w;
            }
        }
    }

    // ---- write partials (unnormalized) ----
    const int base = (qb*KSPLIT + chunk) * 64;
    if (tx == 0) {
        #pragma unroll
        for (int i = 0; i < 4; i++) {
            g_pm[base + ty + 16*i] = m_i[i];
            g_pl[base + ty + 16*i] = l_i[i];
        }
    }
    #pragma unroll
    for (int i = 0; i < 4; i++) {
        size_t ro = (size_t)(base + ty + 16*i) * 128;
        *reinterpret_cast<float4*>(g_pacc + ro + 4*tx) =
            make_float4(acc[i][0], acc[i][1], acc[i][2], acc[i][3]);
        *reinterpret_cast<float4*>(g_pacc + ro + 4*tx + 64) =
            make_float4(acc[i][4], acc[i][5], acc[i][6], acc[i][7]);
    }
}

// ---------------- combine split-K partials + column sum --------------------
__global__ __launch_bounds__(256) void combine_kernel() {
    __shared__ float colsum[128];
    int tid = threadIdx.x;
    if (tid < 128) colsum[tid] = 0.f;
    __syncthreads();
    int w = tid >> 5, lane = tid & 31;
    int row0 = blockIdx.x * 32 + w * 4;
    float o0 = 0.f, o1 = 0.f, o2 = 0.f, o3 = 0.f;
    for (int ii = 0; ii < 4; ii++) {
        int row = row0 + ii;
        if (row >= NN) break;
        int pb = (row >> 6) * KSPLIT;
        int r = row & 63;
        float mv[KSPLIT], lv[KSPLIT];
        float M = -1e30f;
        #pragma unroll
        for (int c = 0; c < KSPLIT; c++) {
            mv[c] = g_pm[(pb + c)*64 + r];
            lv[c] = g_pl[(pb + c)*64 + r];
            M = fmaxf(M, mv[c]);
        }
        float L = 0.f;
        #pragma unroll
        for (int c = 0; c < KSPLIT; c++) L += lv[c] * expf(mv[c] - M);
        float inv = 1.f / L;
        #pragma unroll
        for (int c = 0; c < KSPLIT; c++) {
            float wg = expf(mv[c] - M) * inv;
            float4 a = *reinterpret_cast<const float4*>(
                g_pacc + (size_t)((pb + c)*64 + r) * 128 + lane*4);
            o0 += wg*a.x; o1 += wg*a.y; o2 += wg*a.z; o3 += wg*a.w;
        }
    }
    atomicAdd(&colsum[lane*4 + 0], o0);
    atomicAdd(&colsum[lane*4 + 1], o1);
    atomicAdd(&colsum[lane*4 + 2], o2);
    atomicAdd(&colsum[lane*4 + 3], o3);
    __syncthreads();
    if (tid < 128) atomicAdd(&g_attnsum[tid], colsum[tid]);
}

// ---------------- final head: Wo + MLP + softmax ---------------------------
__global__ void final_kernel(const float* __restrict__ Wo, const float* __restrict__ bo,
        const float* __restrict__ W1, const float* __restrict__ c1,
        const float* __restrict__ W2, const float* __restrict__ c2,
        const float* __restrict__ W3, const float* __restrict__ c3,
        float* __restrict__ out) {
    __shared__ float st[128];
    __shared__ float x1[64];
    __shared__ float x2[32];
    __shared__ float red[128];
    int t = threadIdx.x;   // 128 threads
    const float invN = 1.0f / (float)NN;
    float s = bo[t];
    for (int a = 0; a < 128; a++) s += g_attnsum[a] * invN * Wo[a*128 + t];
    st[t] = s;
    __syncthreads();
    if (t < 64) {
        float v = c1[t];
        for (int a = 0; a < 128; a++) v += st[a] * W1[a*64 + t];
        x1[t] = fmaxf(v, 0.f);
    }
    __syncthreads();
    if (t < 32) {
        float v = c2[t];
        for (int a = 0; a < 64; a++) v += x1[a] * W2[a*32 + t];
        x2[t] = fmaxf(v, 0.f);
    }
    __syncthreads();
    float v3 = c3[t];
    for (int a = 0; a < 32; a++) v3 += x2[a] * W3[a*128 + t];
    red[t] = v3;
    __syncthreads();
    for (int o = 64; o >= 1; o >>= 1) {
        if (t < o) red[t] = fmaxf(red[t], red[t + o]);
        __syncthreads();
    }
    float mx = red[0];
    __syncthreads();
    float e = expf(v3 - mx);
    red[t] = e;
    __syncthreads();
    for (int o = 64; o >= 1; o >>= 1) {
        if (t < o) red[t] += red[t + o];
        __syncthreads();
    }
    out[t] = e / red[0];
}

// ---------------- launch ----------------------------------------------------
extern "C" void kernel_launch(void* const* d_in, const int* in_sizes, int n_in,
                              void* d_out, int out_size) {
    const float* nf      = (const float*)d_in[0];
    const float* gi      = (const float*)d_in[1];
    const int*   ei      = (const int*)  d_in[2];
    const float* W1_root = (const float*)d_in[3];
    const float* W1_rel  = (const float*)d_in[4];
    const float* b1      = (const float*)d_in[5];
    const float* W2_root = (const float*)d_in[6];
    const float* W2_rel  = (const float*)d_in[7];
    const float* b2      = (const float*)d_in[8];
    const float* WQ      = (const float*)d_in[9];
    const float* bQ      = (const float*)d_in[10];
    const float* WK      = (const float*)d_in[11];
    const float* bK      = (const float*)d_in[12];
    const float* WV      = (const float*)d_in[13];
    const float* bV      = (const float*)d_in[14];
    const float* WQg     = (const float*)d_in[15];
    const float* bQg     = (const float*)d_in[16];
    const float* WKg     = (const float*)d_in[17];
    const float* bKg     = (const float*)d_in[18];
    const float* WVg     = (const float*)d_in[19];
    const float* bVg     = (const float*)d_in[20];
    const float* Wo      = (const float*)d_in[21];
    const float* bo      = (const float*)d_in[22];
    const float* Wfc1    = (const float*)d_in[23];
    const float* bfc1    = (const float*)d_in[24];
    const float* Wfc2    = (const float*)d_in[25];
    const float* bfc2    = (const float*)d_in[26];
    const float* Wfc3    = (const float*)d_in[27];
    const float* bfc3    = (const float*)d_in[28];
    float* out = (float*)d_out;

    cudaFuncSetAttribute(conv_kernel<true>,  cudaFuncAttributeMaxDynamicSharedMemorySize, CONV_SMEM);
    cudaFuncSetAttribute(conv_kernel<false>, cudaFuncAttributeMaxDynamicSharedMemorySize, CONV_SMEM);
    cudaFuncSetAttribute(qkv_kernel,         cudaFuncAttributeMaxDynamicSharedMemorySize, QKV_SMEM);
    cudaFuncSetAttribute(attn_kernel,        cudaFuncAttributeMaxDynamicSharedMemorySize, ATTN_SMEM);

    float* agg1;  cudaGetSymbolAddress((void**)&agg1,  g_agg1);
    float* agg2;  cudaGetSymbolAddress((void**)&agg2,  g_agg2);
    float* h;     cudaGetSymbolAddress((void**)&h,     g_h);
    float* embed; cudaGetSymbolAddress((void**)&embed, g_embed);

    const int* src = ei;
    const int* dst = ei + EE;

    zero_kernel<<<(NN*DD + 255)/256, 256>>>();
    scatter_kernel<<<(EE*32)/256, 256>>>(nf, src, dst, agg1);
    conv_kernel<true><<<(NN+31)/32, 256, CONV_SMEM>>>(nf, agg1, W1_root, W1_rel, b1, h);
    scatter_kernel<<<(EE*32)/256, 256>>>(h, src, dst, agg2);
    conv_kernel<false><<<(NN+31)/32, 256, CONV_SMEM>>>(h, agg2, W2_root, W2_rel, b2, embed);
    gbias_kernel<<<1, 384>>>(gi, WQg, bQg, WKg, bKg, WVg, bVg, bQ, bK, bV);
    qkv_kernel<<<(NN+31)/32, 256, QKV_SMEM>>>(WQ, WK, WV);
    attn_kernel<<<dim3(QB, KSPLIT), 256, ATTN_SMEM>>>();
    combine_kernel<<<(NN+31)/32, 256>>>();
    final_kernel<<<1, 128>>>(Wo, bo, Wfc1, bfc1, Wfc2, bfc2, Wfc3, bfc3, out);
}

// round 3
// speedup vs baseline: 1.0004x; 1.0004x over previous
#include <cuda_runtime.h>
#include <math.h>

#define NN 10000
#define EE 160000
#define DD 128
#define QB 157            // ceil(NN/64)
#define KSPLIT 8
#define CHUNK (NN / KSPLIT)   // 1250

// ---------------- scratch (static device arrays; no cudaMalloc) ------------
__device__ float g_agg1[NN*DD];
__device__ float g_agg2[NN*DD];
__device__ float g_h[NN*DD];
__device__ float g_embed[NN*DD];
__device__ float g_Q[NN*DD];
__device__ float g_K[NN*DD];
__device__ float g_V[NN*DD];
__device__ float g_gb[3*DD];          // fused (node bias + global projection) per Q/K/V
__device__ float g_attnsum[DD];       // sum over all output rows of attention
__device__ float g_pm[QB*KSPLIT*64];
__device__ float g_pl[QB*KSPLIT*64];
__device__ float g_pacc[QB*KSPLIT*64*DD];   // ~41 MB partial accumulators

// ---------------- zero scratch --------------------------------------------
__global__ void zero_kernel() {
    int t = blockIdx.x * blockDim.x + threadIdx.x;
    if (t < NN*DD) { g_agg1[t] = 0.f; g_agg2[t] = 0.f; }
    if (t < DD) g_attnsum[t] = 0.f;
}

// ---------------- scatter-add: agg[dst] += x[src] --------------------------
__global__ __launch_bounds__(256) void scatter_kernel(
        const float* __restrict__ x, const int* __restrict__ src,
        const int* __restrict__ dst, float* __restrict__ agg) {
    int t = blockIdx.x * 256 + threadIdx.x;
    int e = t >> 5;
    if (e >= EE) return;
    int fq = (t & 31) << 2;
    int s = __ldg(src + e);
    int d = __ldg(dst + e);
    float4 v = *reinterpret_cast<const float4*>(x + (size_t)s * DD + fq);
    float* p = agg + (size_t)d * DD + fq;
    atomicAdd(p + 0, v.x); atomicAdd(p + 1, v.y);
    atomicAdd(p + 2, v.z); atomicAdd(p + 3, v.w);
}

// ---------------- fused dual GEMM: out = [X|Y] @ [Wa;Wb] + b (opt. relu) ---
// CTA: 256 threads, 32 rows. smem: W 256x128 (128KB) + A 32x256 (32KB)
#define CONV_SMEM ((256*128 + 32*256) * 4)
template<bool RELU>
__global__ __launch_bounds__(256) void conv_kernel(
        const float* __restrict__ X, const float* __restrict__ Y,
        const float* __restrict__ Wa, const float* __restrict__ Wb,
        const float* __restrict__ bias, float* __restrict__ out) {
    extern __shared__ float sm[];
    float* sW = sm;             // [256][128]
    float* sA = sm + 256*128;   // [32][256]
    int tid = threadIdx.x;
    int row0 = blockIdx.x * 32;

    for (int i = tid*4; i < 256*128; i += 1024) {
        float4 v;
        if (i < 128*128) v = *reinterpret_cast<const float4*>(Wa + i);
        else             v = *reinterpret_cast<const float4*>(Wb + (i - 128*128));
        *reinterpret_cast<float4*>(sW + i) = v;
    }
    for (int i = tid*4; i < 32*256; i += 1024) {
        int r = i >> 8, c = i & 255;
        int gr = row0 + r;
        float4 v = make_float4(0.f,0.f,0.f,0.f);
        if (gr < NN) {
            if (c < 128) v = *reinterpret_cast<const float4*>(X + (size_t)gr*128 + c);
            else         v = *reinterpret_cast<const float4*>(Y + (size_t)gr*128 + (c-128));
        }
        *reinterpret_cast<float4*>(sA + i) = v;
    }
    __syncthreads();

    int w = tid >> 5, lane = tid & 31;
    int r0 = w * 4;
    float4 bb = *reinterpret_cast<const float4*>(bias + lane*4);
    float acc[4][4];
    #pragma unroll
    for (int i = 0; i < 4; i++) { acc[i][0]=bb.x; acc[i][1]=bb.y; acc[i][2]=bb.z; acc[i][3]=bb.w; }

    for (int k = 0; k < 256; k += 4) {
        float a0[4], a1[4], a2[4], a3[4];
        #pragma unroll
        for (int i = 0; i < 4; i++) {
            float4 t = *reinterpret_cast<const float4*>(sA + (r0+i)*256 + k);
            a0[i]=t.x; a1[i]=t.y; a2[i]=t.z; a3[i]=t.w;
        }
        float4 b;
        b = *reinterpret_cast<const float4*>(sW + (k+0)*128 + lane*4);
        #pragma unroll
        for (int i=0;i<4;i++){ acc[i][0]+=a0[i]*b.x; acc[i][1]+=a0[i]*b.y; acc[i][2]+=a0[i]*b.z; acc[i][3]+=a0[i]*b.w; }
        b = *reinterpret_cast<const float4*>(sW + (k+1)*128 + lane*4);
        #pragma unroll
        for (int i=0;i<4;i++){ acc[i][0]+=a1[i]*b.x; acc[i][1]+=a1[i]*b.y; acc[i][2]+=a1[i]*b.z; acc[i][3]+=a1[i]*b.w; }
        b = *reinterpret_cast<const float4*>(sW + (k+2)*128 + lane*4);
        #pragma unroll
        for (int i=0;i<4;i++){ acc[i][0]+=a2[i]*b.x; acc[i][1]+=a2[i]*b.y; acc[i][2]+=a2[i]*b.z; acc[i][3]+=a2[i]*b.w; }
        b = *reinterpret_cast<const float4*>(sW + (k+3)*128 + lane*4);
        #pragma unroll
        for (int i=0;i<4;i++){ acc[i][0]+=a3[i]*b.x; acc[i][1]+=a3[i]*b.y; acc[i][2]+=a3[i]*b.z; acc[i][3]+=a3[i]*b.w; }
    }

    #pragma unroll
    for (int i = 0; i < 4; i++) {
        int gr = row0 + r0 + i;
        if (gr < NN) {
            float4 o;
            if (RELU) { o.x=fmaxf(acc[i][0],0.f); o.y=fmaxf(acc[i][1],0.f); o.z=fmaxf(acc[i][2],0.f); o.w=fmaxf(acc[i][3],0.f); }
            else      { o.x=acc[i][0]; o.y=acc[i][1]; o.z=acc[i][2]; o.w=acc[i][3]; }
            *reinterpret_cast<float4*>(out + (size_t)gr*128 + lane*4) = o;
        }
    }
}

// ---------------- global-bias precompute -----------------------------------
__global__ void gbias_kernel(const float* __restrict__ g,
        const float* __restrict__ WQg, const float* __restrict__ bQg,
        const float* __restrict__ WKg, const float* __restrict__ bKg,
        const float* __restrict__ WVg, const float* __restrict__ bVg,
        const float* __restrict__ bQ, const float* __restrict__ bK,
        const float* __restrict__ bV) {
    int t = threadIdx.x;            // 384 threads
    int m = t >> 7, f = t & 127;
    const float* Wg = (m == 0) ? WQg : ((m == 1) ? WKg : WVg);
    const float* bg = (m == 0) ? bQg : ((m == 1) ? bKg : bVg);
    const float* bn = (m == 0) ? bQ  : ((m == 1) ? bK  : bV);
    float s = bg[f] + bn[f];
    for (int d = 0; d < 64; d++) s += g[d] * Wg[d*128 + f];
    g_gb[t] = s;
}

// ---------------- QKV: [Q|K|V] = embed @ [WQ|WK|WV] + g_gb ----------------
#define QKV_SMEM ((128*384 + 32*128) * 4)
__global__ __launch_bounds__(256) void qkv_kernel(
        const float* __restrict__ WQ, const float* __restrict__ WK,
        const float* __restrict__ WV) {
    extern __shared__ float sm[];
    float* sW = sm;              // [128][384]
    float* sA = sm + 128*384;    // [32][128]
    int tid = threadIdx.x;
    int row0 = blockIdx.x * 32;

    for (int i = tid*4; i < 128*384; i += 1024) {
        int k = i / 384, c = i % 384;
        int m = c >> 7, cc = c & 127;
        const float* W = (m == 0) ? WQ : ((m == 1) ? WK : WV);
        *reinterpret_cast<float4*>(sW + i) =
            *reinterpret_cast<const float4*>(W + k*128 + cc);
    }
    for (int i = tid*4; i < 32*128; i += 1024) {
        int r = i >> 7, c = i & 127;
        int gr = row0 + r;
        float4 v = make_float4(0.f,0.f,0.f,0.f);
        if (gr < NN) v = *reinterpret_cast<const float4*>(g_embed + (size_t)gr*128 + c);
        *reinterpret_cast<float4*>(sA + i) = v;
    }
    __syncthreads();

    int w = tid >> 5, lane = tid & 31;
    int r0 = w * 4;
    float acc[4][12];
    {
        float4 q0 = *reinterpret_cast<const float4*>(g_gb + 0*128 + lane*4);
        float4 q1 = *reinterpret_cast<const float4*>(g_gb + 1*128 + lane*4);
        float4 q2 = *reinterpret_cast<const float4*>(g_gb + 2*128 + lane*4);
        #pragma unroll
        for (int i = 0; i < 4; i++) {
            acc[i][0]=q0.x; acc[i][1]=q0.y; acc[i][2]=q0.z; acc[i][3]=q0.w;
            acc[i][4]=q1.x; acc[i][5]=q1.y; acc[i][6]=q1.z; acc[i][7]=q1.w;
            acc[i][8]=q2.x; acc[i][9]=q2.y; acc[i][10]=q2.z; acc[i][11]=q2.w;
        }
    }
    for (int k = 0; k < 128; k++) {
        float4 b0 = *reinterpret_cast<const float4*>(sW + k*384 +   0 + lane*4);
        float4 b1 = *reinterpret_cast<const float4*>(sW + k*384 + 128 + lane*4);
        float4 b2 = *reinterpret_cast<const float4*>(sW + k*384 + 256 + lane*4);
        #pragma unroll
        for (int i = 0; i < 4; i++) {
            float a = sA[(r0+i)*128 + k];
            acc[i][0]+=a*b0.x; acc[i][1]+=a*b0.y; acc[i][2]+=a*b0.z;  acc[i][3]+=a*b0.w;
            acc[i][4]+=a*b1.x; acc[i][5]+=a*b1.y; acc[i][6]+=a*b1.z;  acc[i][7]+=a*b1.w;
            acc[i][8]+=a*b2.x; acc[i][9]+=a*b2.y; acc[i][10]+=a*b2.z; acc[i][11]+=a*b2.w;
        }
    }
    #pragma unroll
    for (int i = 0; i < 4; i++) {
        int gr = row0 + r0 + i;
        if (gr < NN) {
            *reinterpret_cast<float4*>(g_Q + (size_t)gr*128 + lane*4) = make_float4(acc[i][0],acc[i][1],acc[i][2],acc[i][3]);
            *reinterpret_cast<float4*>(g_K + (size_t)gr*128 + lane*4) = make_float4(acc[i][4],acc[i][5],acc[i][6],acc[i][7]);
            *reinterpret_cast<float4*>(g_V + (size_t)gr*128 + lane*4) = make_float4(acc[i][8],acc[i][9],acc[i][10],acc[i][11]);
        }
    }
}

// ---------------- flash attention (split-K partials) -----------------------
// BQ=64, BK=64, 256 threads. Thread (ty,tx): rows ty+16i, S-cols tx+16j,
// PV-cols 4tx+64u+v. Stride 132 (Q/K/V) and 66 (P) -> conflict-free phases.
#define ATTN_SMEM ((3*64*132 + 64*66) * 4)
__global__ __launch_bounds__(256) void attn_kernel() {
    extern __shared__ float sm[];
    float* sQ = sm;                // [64][132]
    float* sK = sQ + 64*132;
    float* sV = sK + 64*132;
    float* sP = sV + 64*132;       // [64][66]
    const int tid = threadIdx.x;
    const int qb = blockIdx.x;
    const int chunk = blockIdx.y;
    const int qrow0 = qb * 64;
    const int kbeg = chunk * CHUNK;
    const int kend = kbeg + CHUNK;

    for (int i = tid*4; i < 64*128; i += 1024) {
        int r = i >> 7, c = i & 127;
        int gr = qrow0 + r;
        float4 v = make_float4(0.f,0.f,0.f,0.f);
        if (gr < NN) v = *reinterpret_cast<const float4*>(g_Q + (size_t)gr*128 + c);
        *reinterpret_cast<float4*>(sQ + r*132 + c) = v;
    }

    const int ty = tid >> 4;   // 0..15
    const int tx = tid & 15;   // 0..15
    float m_i[4], l_i[4], acc[4][8];
    #pragma unroll
    for (int i = 0; i < 4; i++) {
        m_i[i] = -1e30f; l_i[i] = 0.f;
        #pragma unroll
        for (int j = 0; j < 8; j++) acc[i][j] = 0.f;
    }
    const float scale = 0.088388347648318447f;   // 1/sqrt(128)

    for (int kt = kbeg; kt < kend; kt += 64) {
        const int kn = min(64, kend - kt);
        __syncthreads();   // prior PV reads done before overwriting K/V/P
        for (int i = tid*4; i < 64*128; i += 1024) {
            int r = i >> 7, c = i & 127;
            float4 kv = make_float4(0.f,0.f,0.f,0.f);
            float4 vv = make_float4(0.f,0.f,0.f,0.f);
            if (r < kn) {
                kv = *reinterpret_cast<const float4*>(g_K + (size_t)(kt+r)*128 + c);
                vv = *reinterpret_cast<const float4*>(g_V + (size_t)(kt+r)*128 + c);
            }
            *reinterpret_cast<float4*>(sK + r*132 + c) = kv;
            *reinterpret_cast<float4*>(sV + r*132 + c) = vv;
        }
        __syncthreads();

        // ---- S = Q K^T (4x4 per thread) ----
        float s[4][4];
        #pragma unroll
        for (int i = 0; i < 4; i++)
            #pragma unroll
            for (int j = 0; j < 4; j++) s[i][j] = 0.f;

        for (int k = 0; k < 128; k += 4) {
            float4 qv[4], kv[4];
            #pragma unroll
            for (int i = 0; i < 4; i++)
                qv[i] = *reinterpret_cast<const float4*>(sQ + (ty+16*i)*132 + k);
            #pragma unroll
            for (int j = 0; j < 4; j++)
                kv[j] = *reinterpret_cast<const float4*>(sK + (tx+16*j)*132 + k);
            #pragma unroll
            for (int i = 0; i < 4; i++)
                #pragma unroll
                for (int j = 0; j < 4; j++)
                    s[i][j] += qv[i].x*kv[j].x + qv[i].y*kv[j].y
                             + qv[i].z*kv[j].z + qv[i].w*kv[j].w;
        }
        #pragma unroll
        for (int j = 0; j < 4; j++) {
            bool valid = (tx + 16*j) < kn;
            #pragma unroll
            for (int i = 0; i < 4; i++)
                s[i][j] = valid ? s[i][j] * scale : -1e30f;
        }

        // ---- online softmax update per row ----
        #pragma unroll
        for (int i = 0; i < 4; i++) {
            float rm = fmaxf(fmaxf(s[i][0], s[i][1]), fmaxf(s[i][2], s[i][3]));
            rm = fmaxf(rm, __shfl_xor_sync(0xffffffffu, rm, 1));
            rm = fmaxf(rm, __shfl_xor_sync(0xffffffffu, rm, 2));
            rm = fmaxf(rm, __shfl_xor_sync(0xffffffffu, rm, 4));
            rm = fmaxf(rm, __shfl_xor_sync(0xffffffffu, rm, 8));
            float mnew = fmaxf(m_i[i], rm);
            float sc = expf(m_i[i] - mnew);
            float p0 = expf(s[i][0] - mnew);
            float p1 = expf(s[i][1] - mnew);
            float p2 = expf(s[i][2] - mnew);
            float p3 = expf(s[i][3] - mnew);
            float rs = p0 + p1 + p2 + p3;
            rs += __shfl_xor_sync(0xffffffffu, rs, 1);
            rs += __shfl_xor_sync(0xffffffffu, rs, 2);
            rs += __shfl_xor_sync(0xffffffffu, rs, 4);
            rs += __shfl_xor_sync(0xffffffffu, rs, 8);
            l_i[i] = l_i[i] * sc + rs;
            m_i[i] = mnew;
            #pragma unroll
            for (int j = 0; j < 8; j++) acc[i][j] *= sc;
            float* pr = sP + (ty + 16*i) * 66;
            pr[tx     ] = p0;
            pr[tx + 16] = p1;
            pr[tx + 32] = p2;
            pr[tx + 48] = p3;
        }
        __syncthreads();

        // ---- acc += P @ V ----
        for (int k2 = 0; k2 < 64; k2++) {
            float4 v0 = *reinterpret_cast<const float4*>(sV + k2*132 + 4*tx);
            float4 v1 = *reinterpret_cast<const float4*>(sV + k2*132 + 4*tx + 64);
            #pragma unroll
            for (int i = 0; i < 4; i++) {
                float p = sP[(ty + 16*i)*66 + k2];
                acc[i][0] += p*v0.x; acc[i][1] += p*v0.y;
                acc[i][2] += p*v0.z; acc[i][3] += p*v0.w;
                acc[i][4] += p*v1.x; acc[i][5] += p*v1.y;
                acc[i][6] += p*v1.z; acc[i][7] += p*v1.w;
            }
        }
    }

    // ---- write partials (unnormalized) ----
    const int base = (qb*KSPLIT + chunk) * 64;
    if (tx == 0) {
        #pragma unroll
        for (int i = 0; i < 4; i++) {
            g_pm[base + ty + 16*i] = m_i[i];
            g_pl[base + ty + 16*i] = l_i[i];
        }
    }
    #pragma unroll
    for (int i = 0; i < 4; i++) {
        size_t ro = (size_t)(base + ty + 16*i) * 128;
        *reinterpret_cast<float4*>(g_pacc + ro + 4*tx) =
            make_float4(acc[i][0], acc[i][1], acc[i][2], acc[i][3]);
        *reinterpret_cast<float4*>(g_pacc + ro + 4*tx + 64) =
            make_float4(acc[i][4], acc[i][5], acc[i][6], acc[i][7]);
    }
}

// ---------------- combine split-K partials + column sum --------------------
__global__ __launch_bounds__(256) void combine_kernel() {
    __shared__ float colsum[128];
    int tid = threadIdx.x;
    if (tid < 128) colsum[tid] = 0.f;
    __syncthreads();
    int w = tid >> 5, lane = tid & 31;
    int row0 = blockIdx.x * 32 + w * 4;
    float o0 = 0.f, o1 = 0.f, o2 = 0.f, o3 = 0.f;
    for (int ii = 0; ii < 4; ii++) {
        int row = row0 + ii;
        if (row >= NN) break;
        int pb = (row >> 6) * KSPLIT;
        int r = row & 63;
        float mv[KSPLIT], lv[KSPLIT];
        float M = -1e30f;
        #pragma unroll
        for (int c = 0; c < KSPLIT; c++) {
            mv[c] = g_pm[(pb + c)*64 + r];
            lv[c] = g_pl[(pb + c)*64 + r];
            M = fmaxf(M, mv[c]);
        }
        float L = 0.f;
        #pragma unroll
        for (int c = 0; c < KSPLIT; c++) L += lv[c] * expf(mv[c] - M);
        float inv = 1.f / L;
        #pragma unroll
        for (int c = 0; c < KSPLIT; c++) {
            float wg = expf(mv[c] - M) * inv;
            float4 a = *reinterpret_cast<const float4*>(
                g_pacc + (size_t)((pb + c)*64 + r) * 128 + lane*4);
            o0 += wg*a.x; o1 += wg*a.y; o2 += wg*a.z; o3 += wg*a.w;
        }
    }
    atomicAdd(&colsum[lane*4 + 0], o0);
    atomicAdd(&colsum[lane*4 + 1], o1);
    atomicAdd(&colsum[lane*4 + 2], o2);
    atomicAdd(&colsum[lane*4 + 3], o3);
    __syncthreads();
    if (tid < 128) atomicAdd(&g_attnsum[tid], colsum[tid]);
}

// ---------------- final head: Wo + MLP + softmax ---------------------------
__global__ void final_kernel(const float* __restrict__ Wo, const float* __restrict__ bo,
        const float* __restrict__ W1, const float* __restrict__ c1,
        const float* __restrict__ W2, const float* __restrict__ c2,
        const float* __restrict__ W3, const float* __restrict__ c3,
        float* __restrict__ out) {
    __shared__ float st[128];
    __shared__ float x1[64];
    __shared__ float x2[32];
    __shared__ float red[128];
    int t = threadIdx.x;   // 128 threads
    const float invN = 1.0f / (float)NN;
    float s = bo[t];
    for (int a = 0; a < 128; a++) s += g_attnsum[a] * invN * Wo[a*128 + t];
    st[t] = s;
    __syncthreads();
    if (t < 64) {
        float v = c1[t];
        for (int a = 0; a < 128; a++) v += st[a] * W1[a*64 + t];
        x1[t] = fmaxf(v, 0.f);
    }
    __syncthreads();
    if (t < 32) {
        float v = c2[t];
        for (int a = 0; a < 64; a++) v += x1[a] * W2[a*32 + t];
        x2[t] = fmaxf(v, 0.f);
    }
    __syncthreads();
    float v3 = c3[t];
    for (int a = 0; a < 32; a++) v3 += x2[a] * W3[a*128 + t];
    red[t] = v3;
    __syncthreads();
    for (int o = 64; o >= 1; o >>= 1) {
        if (t < o) red[t] = fmaxf(red[t], red[t + o]);
        __syncthreads();
    }
    float mx = red[0];
    __syncthreads();
    float e = expf(v3 - mx);
    red[t] = e;
    __syncthreads();
    for (int o = 64; o >= 1; o >>= 1) {
        if (t < o) red[t] += red[t + o];
        __syncthreads();
    }
    out[t] = e / red[0];
}

// ---------------- launch ----------------------------------------------------
extern "C" void kernel_launch(void* const* d_in, const int* in_sizes, int n_in,
                              void* d_out, int out_size) {
    const float* nf      = (const float*)d_in[0];
    const float* gi      = (const float*)d_in[1];
    const int*   ei      = (const int*)  d_in[2];
    const float* W1_root = (const float*)d_in[3];
    const float* W1_rel  = (const float*)d_in[4];
    const float* b1      = (const float*)d_in[5];
    const float* W2_root = (const float*)d_in[6];
    const float* W2_rel  = (const float*)d_in[7];
    const float* b2      = (const float*)d_in[8];
    const float* WQ      = (const float*)d_in[9];
    const float* bQ      = (const float*)d_in[10];
    const float* WK      = (const float*)d_in[11];
    const float* bK      = (const float*)d_in[12];
    const float* WV      = (const float*)d_in[13];
    const float* bV      = (const float*)d_in[14];
    const float* WQg     = (const float*)d_in[15];
    const float* bQg     = (const float*)d_in[16];
    const float* WKg     = (const float*)d_in[17];
    const float* bKg     = (const float*)d_in[18];
    const float* WVg     = (const float*)d_in[19];
    const float* bVg     = (const float*)d_in[20];
    const float* Wo      = (const float*)d_in[21];
    const float* bo      = (const float*)d_in[22];
    const float* Wfc1    = (const float*)d_in[23];
    const float* bfc1    = (const float*)d_in[24];
    const float* Wfc2    = (const float*)d_in[25];
    const float* bfc2    = (const float*)d_in[26];
    const float* Wfc3    = (const float*)d_in[27];
    const float* bfc3    = (const float*)d_in[28];
    float* out = (float*)d_out;

    cudaFuncSetAttribute(conv_kernel<true>,  cudaFuncAttributeMaxDynamicSharedMemorySize, CONV_SMEM);
    cudaFuncSetAttribute(conv_kernel<false>, cudaFuncAttributeMaxDynamicSharedMemorySize, CONV_SMEM);
    cudaFuncSetAttribute(qkv_kernel,         cudaFuncAttributeMaxDynamicSharedMemorySize, QKV_SMEM);
    cudaFuncSetAttribute(attn_kernel,        cudaFuncAttributeMaxDynamicSharedMemorySize, ATTN_SMEM);

    float* agg1;  cudaGetSymbolAddress((void**)&agg1,  g_agg1);
    float* agg2;  cudaGetSymbolAddress((void**)&agg2,  g_agg2);
    float* h;     cudaGetSymbolAddress((void**)&h,     g_h);
    float* embed; cudaGetSymbolAddress((void**)&embed, g_embed);

    const int* src = ei;
    const int* dst = ei + EE;

    zero_kernel<<<(NN*DD + 255)/256, 256>>>();
    scatter_kernel<<<(EE*32)/256, 256>>>(nf, src, dst, agg1);
    conv_kernel<true><<<(NN+31)/32, 256, CONV_SMEM>>>(nf, agg1, W1_root, W1_rel, b1, h);
    scatter_kernel<<<(EE*32)/256, 256>>>(h, src, dst, agg2);
    conv_kernel<false><<<(NN+31)/32, 256, CONV_SMEM>>>(h, agg2, W2_root, W2_rel, b2, embed);
    gbias_kernel<<<1, 384>>>(gi, WQg, bQg, WKg, bKg, WVg, bVg, bQ, bK, bV);
    qkv_kernel<<<(NN+31)/32, 256, QKV_SMEM>>>(WQ, WK, WV);
    attn_kernel<<<dim3(QB, KSPLIT), 256, ATTN_SMEM>>>();
    combine_kernel<<<(NN+31)/32, 256>>>();
    final_kernel<<<1, 128>>>(Wo, bo, Wfc1, bfc1, Wfc2, bfc2, Wfc3, bfc3, out);
}

// round 6
// speedup vs baseline: 2.8759x; 2.8748x over previous
#include <cuda_runtime.h>
#include <cuda_bf16.h>
#include <math.h>
#include <stdint.h>

#define NN 10000
#define EE 160000
#define DD 128
#define AQB 79
#define AKS 13

extern __shared__ char smem_raw[];

// attn smem layout (bytes)
#define AT_QH 0
#define AT_QL 32768
#define AT_KH 65536
#define AT_KL 81920
#define AT_VH 98304
#define AT_VL 114688
#define AT_SMEM 131072

__device__ __forceinline__ uint32_t smem_u32(const void* p) {
    uint32_t a; asm("{ .reg .u64 t; cvta.to.shared.u64 t, %1; cvt.u32.u64 %0, t; }":"=r"(a):"l"(p)); return a;
}
__device__ __forceinline__ float ex2(float x){ float y; asm("ex2.approx.ftz.f32 %0, %1;":"=f"(y):"f"(x)); return y; }

// fast 2^f on the FMA pipe (f <= 0); ~6e-5 rel err, clamped at 2^-120
__device__ __forceinline__ float exp2p(float f) {
    f = fmaxf(f, -120.f);
    float n = rintf(f);
    float r = f - n;
    float p = 0.00961812911f;
    p = fmaf(p, r, 0.05550410866f);
    p = fmaf(p, r, 0.24022650696f);
    p = fmaf(p, r, 0.69314718056f);
    p = fmaf(p, r, 1.0f);
    return p * __int_as_float(((int)n + 127) << 23);
}

#define LDSM4(R, A) asm volatile("ldmatrix.sync.aligned.m8n8.x4.shared.b16 {%0,%1,%2,%3}, [%4];" \
    : "=r"((R)[0]),"=r"((R)[1]),"=r"((R)[2]),"=r"((R)[3]) : "r"(A))
#define LDSM4T(R, A) asm volatile("ldmatrix.sync.aligned.m8n8.x4.trans.shared.b16 {%0,%1,%2,%3}, [%4];" \
    : "=r"((R)[0]),"=r"((R)[1]),"=r"((R)[2]),"=r"((R)[3]) : "r"(A))
#define MMA16816(D, A, B0, B1) asm volatile( \
    "mma.sync.aligned.m16n8k16.row.col.f32.bf16.bf16.f32 {%0,%1,%2,%3}, {%4,%5,%6,%7}, {%8,%9}, {%0,%1,%2,%3};" \
    : "+f"((D)[0]),"+f"((D)[1]),"+f"((D)[2]),"+f"((D)[3]) \
    : "r"((A)[0]),"r"((A)[1]),"r"((A)[2]),"r"((A)[3]), "r"(B0),"r"(B1))

// ---------------- scratch ----------------
__device__ float g_agg1[NN*DD];
__device__ float g_agg2[NN*DD];
__device__ float g_h[NN*DD];
__device__ float g_embed[NN*DD];
__device__ __nv_bfloat16 g_Qh[NN*DD], g_Ql[NN*DD], g_Kh[NN*DD], g_Kl[NN*DD];
__device__ __nv_bfloat16 g_Vh[NN*DD], g_Vl[NN*DD];
__device__ float g_gb[3*DD];
__device__ float g_attnsum[DD];
__device__ float g_pm[AQB*AKS*128];
__device__ float g_pl[AQB*AKS*128];
__device__ float g_pacc[(size_t)AQB*AKS*128*128];

__global__ void zero_kernel() {
    int t = blockIdx.x * blockDim.x + threadIdx.x;
    if (t < NN*DD) { g_agg1[t] = 0.f; g_agg2[t] = 0.f; }
    if (t < DD) g_attnsum[t] = 0.f;
}

__global__ __launch_bounds__(256) void scatter_kernel(
        const float* __restrict__ x, const int* __restrict__ src,
        const int* __restrict__ dst, float* __restrict__ agg) {
    int t = blockIdx.x * 256 + threadIdx.x;
    int e = t >> 5;
    if (e >= EE) return;
    int fq = (t & 31) << 2;
    int s = __ldg(src + e), d = __ldg(dst + e);
    float4 v = *reinterpret_cast<const float4*>(x + (size_t)s * DD + fq);
    float* p = agg + (size_t)d * DD + fq;
    atomicAdd(p + 0, v.x); atomicAdd(p + 1, v.y);
    atomicAdd(p + 2, v.z); atomicAdd(p + 3, v.w);
}

#define CONV_SMEM ((256*128 + 32*256) * 4)
template<bool RELU>
__global__ __launch_bounds__(256) void conv_kernel(
        const float* __restrict__ X, const float* __restrict__ Y,
        const float* __restrict__ Wa, const float* __restrict__ Wb,
        const float* __restrict__ bias, float* __restrict__ out) {
    float* sm = (float*)smem_raw;
    float* sW = sm;
    float* sA = sm + 256*128;
    int tid = threadIdx.x;
    int row0 = blockIdx.x * 32;
    for (int i = tid*4; i < 256*128; i += 1024) {
        float4 v;
        if (i < 128*128) v = *reinterpret_cast<const float4*>(Wa + i);
        else             v = *reinterpret_cast<const float4*>(Wb + (i - 128*128));
        *reinterpret_cast<float4*>(sW + i) = v;
    }
    for (int i = tid*4; i < 32*256; i += 1024) {
        int r = i >> 8, c = i & 255;
        int gr = row0 + r;
        float4 v = make_float4(0.f,0.f,0.f,0.f);
        if (gr < NN) {
            if (c < 128) v = *reinterpret_cast<const float4*>(X + (size_t)gr*128 + c);
            else         v = *reinterpret_cast<const float4*>(Y + (size_t)gr*128 + (c-128));
        }
        *reinterpret_cast<float4*>(sA + i) = v;
    }
    __syncthreads();
    int w = tid >> 5, lane = tid & 31;
    int r0 = w * 4;
    float4 bb = *reinterpret_cast<const float4*>(bias + lane*4);
    float acc[4][4];
    #pragma unroll
    for (int i = 0; i < 4; i++) { acc[i][0]=bb.x; acc[i][1]=bb.y; acc[i][2]=bb.z; acc[i][3]=bb.w; }
    for (int k = 0; k < 256; k += 4) {
        float a0[4], a1[4], a2[4], a3[4];
        #pragma unroll
        for (int i = 0; i < 4; i++) {
            float4 t = *reinterpret_cast<const float4*>(sA + (r0+i)*256 + k);
            a0[i]=t.x; a1[i]=t.y; a2[i]=t.z; a3[i]=t.w;
        }
        float4 b;
        b = *reinterpret_cast<const float4*>(sW + (k+0)*128 + lane*4);
        #pragma unroll
        for (int i=0;i<4;i++){ acc[i][0]+=a0[i]*b.x; acc[i][1]+=a0[i]*b.y; acc[i][2]+=a0[i]*b.z; acc[i][3]+=a0[i]*b.w; }
        b = *reinterpret_cast<const float4*>(sW + (k+1)*128 + lane*4);
        #pragma unroll
        for (int i=0;i<4;i++){ acc[i][0]+=a1[i]*b.x; acc[i][1]+=a1[i]*b.y; acc[i][2]+=a1[i]*b.z; acc[i][3]+=a1[i]*b.w; }
        b = *reinterpret_cast<const float4*>(sW + (k+2)*128 + lane*4);
        #pragma unroll
        for (int i=0;i<4;i++){ acc[i][0]+=a2[i]*b.x; acc[i][1]+=a2[i]*b.y; acc[i][2]+=a2[i]*b.z; acc[i][3]+=a2[i]*b.w; }
        b = *reinterpret_cast<const float4*>(sW + (k+3)*128 + lane*4);
        #pragma unroll
        for (int i=0;i<4;i++){ acc[i][0]+=a3[i]*b.x; acc[i][1]+=a3[i]*b.y; acc[i][2]+=a3[i]*b.z; acc[i][3]+=a3[i]*b.w; }
    }
    #pragma unroll
    for (int i = 0; i < 4; i++) {
        int gr = row0 + r0 + i;
        if (gr < NN) {
            float4 o;
            if (RELU) { o.x=fmaxf(acc[i][0],0.f); o.y=fmaxf(acc[i][1],0.f); o.z=fmaxf(acc[i][2],0.f); o.w=fmaxf(acc[i][3],0.f); }
            else      { o.x=acc[i][0]; o.y=acc[i][1]; o.z=acc[i][2]; o.w=acc[i][3]; }
            *reinterpret_cast<float4*>(out + (size_t)gr*128 + lane*4) = o;
        }
    }
}

__global__ void gbias_kernel(const float* __restrict__ g,
        const float* __restrict__ WQg, const float* __restrict__ bQg,
        const float* __restrict__ WKg, const float* __restrict__ bKg,
        const float* __restrict__ WVg, const float* __restrict__ bVg,
        const float* __restrict__ bQ, const float* __restrict__ bK,
        const float* __restrict__ bV) {
    int t = threadIdx.x;
    int m = t >> 7, f = t & 127;
    const float* Wg = (m == 0) ? WQg : ((m == 1) ? WKg : WVg);
    const float* bg = (m == 0) ? bQg : ((m == 1) ? bKg : bVg);
    const float* bn = (m == 0) ? bQ  : ((m == 1) ? bK  : bV);
    float s = bg[f] + bn[f];
    for (int d = 0; d < 64; d++) s += g[d] * Wg[d*128 + f];
    g_gb[t] = s;
}

__device__ __forceinline__ void cvt4(const float* a, uint2& hh, uint2& ll) {
    __nv_bfloat16 h0=__float2bfloat16_rn(a[0]), h1=__float2bfloat16_rn(a[1]);
    __nv_bfloat16 h2=__float2bfloat16_rn(a[2]), h3=__float2bfloat16_rn(a[3]);
    __nv_bfloat16 l0=__float2bfloat16_rn(a[0]-__bfloat162float(h0));
    __nv_bfloat16 l1=__float2bfloat16_rn(a[1]-__bfloat162float(h1));
    __nv_bfloat16 l2=__float2bfloat16_rn(a[2]-__bfloat162float(h2));
    __nv_bfloat16 l3=__float2bfloat16_rn(a[3]-__bfloat162float(h3));
    __nv_bfloat162 H0{h0,h1}, H1{h2,h3}, L0{l0,l1}, L1{l2,l3};
    hh = make_uint2(*(uint32_t*)&H0, *(uint32_t*)&H1);
    ll = make_uint2(*(uint32_t*)&L0, *(uint32_t*)&L1);
}

#define QKV_SMEM ((128*384 + 32*128) * 4)
__global__ __launch_bounds__(256) void qkv_kernel(
        const float* __restrict__ WQ, const float* __restrict__ WK,
        const float* __restrict__ WV) {
    float* sm = (float*)smem_raw;
    float* sW = sm;
    float* sA = sm + 128*384;
    int tid = threadIdx.x;
    int row0 = blockIdx.x * 32;
    const float CQ = 0.08838834764831845f * 1.4426950408889634f;  // 1/sqrt(128)*log2(e)
    for (int i = tid*4; i < 128*384; i += 1024) {
        int k = i / 384, c = i % 384;
        int m = c >> 7, cc = c & 127;
        const float* W = (m == 0) ? WQ : ((m == 1) ? WK : WV);
        *reinterpret_cast<float4*>(sW + i) = *reinterpret_cast<const float4*>(W + k*128 + cc);
    }
    for (int i = tid*4; i < 32*128; i += 1024) {
        int r = i >> 7, c = i & 127;
        int gr = row0 + r;
        float4 v = make_float4(0.f,0.f,0.f,0.f);
        if (gr < NN) v = *reinterpret_cast<const float4*>(g_embed + (size_t)gr*128 + c);
        *reinterpret_cast<float4*>(sA + i) = v;
    }
    __syncthreads();
    int w = tid >> 5, lane = tid & 31;
    int r0 = w * 4;
    float acc[4][12];
    {
        float4 q0 = *reinterpret_cast<const float4*>(g_gb + 0*128 + lane*4);
        float4 q1 = *reinterpret_cast<const float4*>(g_gb + 1*128 + lane*4);
        float4 q2 = *reinterpret_cast<const float4*>(g_gb + 2*128 + lane*4);
        #pragma unroll
        for (int i = 0; i < 4; i++) {
            acc[i][0]=q0.x; acc[i][1]=q0.y; acc[i][2]=q0.z; acc[i][3]=q0.w;
            acc[i][4]=q1.x; acc[i][5]=q1.y; acc[i][6]=q1.z; acc[i][7]=q1.w;
            acc[i][8]=q2.x; acc[i][9]=q2.y; acc[i][10]=q2.z; acc[i][11]=q2.w;
        }
    }
    for (int k = 0; k < 128; k++) {
        float4 b0 = *reinterpret_cast<const float4*>(sW + k*384 +   0 + lane*4);
        float4 b1 = *reinterpret_cast<const float4*>(sW + k*384 + 128 + lane*4);
        float4 b2 = *reinterpret_cast<const float4*>(sW + k*384 + 256 + lane*4);
        #pragma unroll
        for (int i = 0; i < 4; i++) {
            float a = sA[(r0+i)*128 + k];
            acc[i][0]+=a*b0.x; acc[i][1]+=a*b0.y; acc[i][2]+=a*b0.z;  acc[i][3]+=a*b0.w;
            acc[i][4]+=a*b1.x; acc[i][5]+=a*b1.y; acc[i][6]+=a*b1.z;  acc[i][7]+=a*b1.w;
            acc[i][8]+=a*b2.x; acc[i][9]+=a*b2.y; acc[i][10]+=a*b2.z; acc[i][11]+=a*b2.w;
        }
    }
    #pragma unroll
    for (int i = 0; i < 4; i++) {
        int gr = row0 + r0 + i;
        if (gr < NN) {
            uint2 hh, ll;
            float qs[4] = {acc[i][0]*CQ, acc[i][1]*CQ, acc[i][2]*CQ, acc[i][3]*CQ};
            cvt4(qs, hh, ll);
            *(uint2*)&g_Qh[(size_t)gr*128 + lane*4] = hh;
            *(uint2*)&g_Ql[(size_t)gr*128 + lane*4] = ll;
            cvt4(&acc[i][4], hh, ll);
            *(uint2*)&g_Kh[(size_t)gr*128 + lane*4] = hh;
            *(uint2*)&g_Kl[(size_t)gr*128 + lane*4] = ll;
            cvt4(&acc[i][8], hh, ll);
            *(uint2*)&g_Vh[(size_t)gr*128 + lane*4] = hh;
            *(uint2*)&g_Vl[(size_t)gr*128 + lane*4] = ll;
        }
    }
}

// ---------------- mma.sync flash attention (split-K partials) --------------
// 8 warps; warp w owns q-rows [16w,16w+16). BK=64. S in log2 domain.
__global__ __launch_bounds__(256, 1) void attn_kernel() {
    char* sm = smem_raw;
    uint32_t sb = smem_u32(sm);
    const int tid = threadIdx.x, wid = tid >> 5, lane = tid & 31;
    const int qb = blockIdx.x, sp = blockIdx.y;
    const int q0 = qb * 128;
    const int kbeg = sp * 768;
    const int kend = (sp == AKS-1) ? NN : kbeg + 768;

    // stage Q hi/lo (swizzled 16B chunks)
    for (int t = tid; t < 2048; t += 256) {
        int r = t >> 4, c = t & 15;
        int gr = q0 + r;
        uint4 vh = make_uint4(0,0,0,0), vl = make_uint4(0,0,0,0);
        if (gr < NN) {
            vh = *(const uint4*)&g_Qh[(size_t)gr*128 + c*8];
            vl = *(const uint4*)&g_Ql[(size_t)gr*128 + c*8];
        }
        uint32_t off = (uint32_t)(r*256 + ((c ^ (r & 7)) << 4));
        *(uint4*)(sm + AT_QH + off) = vh;
        *(uint4*)(sm + AT_QL + off) = vl;
    }
    __syncthreads();

    const int g8 = lane >> 3, i8 = lane & 7;
    uint32_t qh[8][4], ql[8][4];
    {
        int row = wid*16 + i8 + ((g8 & 1) << 3);
        #pragma unroll
        for (int t = 0; t < 8; t++) {
            uint32_t ch = (uint32_t)((2*t + (g8 >> 1)) ^ (row & 7));
            uint32_t off = (uint32_t)(row*256) + (ch << 4);
            LDSM4(qh[t], sb + AT_QH + off);
            LDSM4(ql[t], sb + AT_QL + off);
        }
    }

    float m0 = -1e30f, m1 = -1e30f, l0 = 0.f, l1 = 0.f;
    float o[16][4];
    #pragma unroll
    for (int j = 0; j < 16; j++) { o[j][0]=0.f; o[j][1]=0.f; o[j][2]=0.f; o[j][3]=0.f; }

    for (int kt = kbeg; kt < kend; kt += 64) {
        const int kn = min(64, kend - kt);
        __syncthreads();
        for (int t = tid; t < 1024; t += 256) {
            int r = t >> 4, c = t & 15;
            uint4 kh = make_uint4(0,0,0,0), kl = kh, vh = kh, vl = kh;
            if (r < kn) {
                size_t go = (size_t)(kt + r)*128 + c*8;
                kh = *(const uint4*)&g_Kh[go];
                kl = *(const uint4*)&g_Kl[go];
                vh = *(const uint4*)&g_Vh[go];
                vl = *(const uint4*)&g_Vl[go];
            }
            uint32_t off = (uint32_t)(r*256 + ((c ^ (r & 7)) << 4));
            *(uint4*)(sm + AT_KH + off) = kh;
            *(uint4*)(sm + AT_KL + off) = kl;
            *(uint4*)(sm + AT_VH + off) = vh;
            *(uint4*)(sm + AT_VL + off) = vl;
        }
        __syncthreads();

        // S = Qh*Kh + Qh*Kl + Ql*Kh   (16x64 per warp)
        float s[8][4];
        #pragma unroll
        for (int j = 0; j < 8; j++) { s[j][0]=0.f; s[j][1]=0.f; s[j][2]=0.f; s[j][3]=0.f; }
        #pragma unroll
        for (int t = 0; t < 8; t++) {
            #pragma unroll
            for (int jp = 0; jp < 4; jp++) {
                int row = 16*jp + i8 + ((g8 >> 1) << 3);
                uint32_t ch = (uint32_t)((2*t + (g8 & 1)) ^ (row & 7));
                uint32_t off = (uint32_t)(row*256) + (ch << 4);
                uint32_t kb[4];
                LDSM4(kb, sb + AT_KH + off);
                MMA16816(s[2*jp],   qh[t], kb[0], kb[1]);
                MMA16816(s[2*jp+1], qh[t], kb[2], kb[3]);
                MMA16816(s[2*jp],   ql[t], kb[0], kb[1]);
                MMA16816(s[2*jp+1], ql[t], kb[2], kb[3]);
                LDSM4(kb, sb + AT_KL + off);
                MMA16816(s[2*jp],   qh[t], kb[0], kb[1]);
                MMA16816(s[2*jp+1], qh[t], kb[2], kb[3]);
            }
        }

        if (kn < 64) {
            int cb = (lane & 3)*2;
            #pragma unroll
            for (int j = 0; j < 8; j++)
                if (8*j + cb >= kn) { s[j][0]=-1e30f; s[j][1]=-1e30f; s[j][2]=-1e30f; s[j][3]=-1e30f; }
        }

        float rm0 = -1e30f, rm1 = -1e30f;
        #pragma unroll
        for (int j = 0; j < 8; j++) {
            rm0 = fmaxf(rm0, fmaxf(s[j][0], s[j][1]));
            rm1 = fmaxf(rm1, fmaxf(s[j][2], s[j][3]));
        }
        rm0 = fmaxf(rm0, __shfl_xor_sync(0xffffffffu, rm0, 1));
        rm0 = fmaxf(rm0, __shfl_xor_sync(0xffffffffu, rm0, 2));
        rm1 = fmaxf(rm1, __shfl_xor_sync(0xffffffffu, rm1, 1));
        rm1 = fmaxf(rm1, __shfl_xor_sync(0xffffffffu, rm1, 2));
        float mn0 = fmaxf(m0, rm0), mn1 = fmaxf(m1, rm1);
        float a0 = exp2p(m0 - mn0), a1 = exp2p(m1 - mn1);
        m0 = mn0; m1 = mn1;

        float sum0 = 0.f, sum1 = 0.f;
        #pragma unroll
        for (int j = 0; j < 8; j++) {
            s[j][0] = exp2p(s[j][0] - mn0); s[j][1] = exp2p(s[j][1] - mn0);
            s[j][2] = exp2p(s[j][2] - mn1); s[j][3] = exp2p(s[j][3] - mn1);
            sum0 += s[j][0] + s[j][1]; sum1 += s[j][2] + s[j][3];
        }
        sum0 += __shfl_xor_sync(0xffffffffu, sum0, 1);
        sum0 += __shfl_xor_sync(0xffffffffu, sum0, 2);
        sum1 += __shfl_xor_sync(0xffffffffu, sum1, 1);
        sum1 += __shfl_xor_sync(0xffffffffu, sum1, 2);
        l0 = l0*a0 + sum0; l1 = l1*a1 + sum1;

        uint32_t pa[4][4];
        #pragma unroll
        for (int t2 = 0; t2 < 4; t2++) {
            __nv_bfloat162 b;
            b = __floats2bfloat162_rn(s[2*t2][0],   s[2*t2][1]);   pa[t2][0] = *(uint32_t*)&b;
            b = __floats2bfloat162_rn(s[2*t2][2],   s[2*t2][3]);   pa[t2][1] = *(uint32_t*)&b;
            b = __floats2bfloat162_rn(s[2*t2+1][0], s[2*t2+1][1]); pa[t2][2] = *(uint32_t*)&b;
            b = __floats2bfloat162_rn(s[2*t2+1][2], s[2*t2+1][3]); pa[t2][3] = *(uint32_t*)&b;
        }

        if (!__all_sync(0xffffffffu, (a0 == 1.f) && (a1 == 1.f))) {
            #pragma unroll
            for (int j = 0; j < 16; j++) {
                o[j][0]*=a0; o[j][1]*=a0; o[j][2]*=a1; o[j][3]*=a1;
            }
        }

        // O += P @ (Vh + Vl)
        #pragma unroll
        for (int t2 = 0; t2 < 4; t2++) {
            #pragma unroll
            for (int jp = 0; jp < 8; jp++) {
                int row = 16*t2 + i8 + ((g8 & 1) << 3);
                uint32_t ch = (uint32_t)((2*jp + (g8 >> 1)) ^ (row & 7));
                uint32_t off = (uint32_t)(row*256) + (ch << 4);
                uint32_t vb[4];
                LDSM4T(vb, sb + AT_VH + off);
                MMA16816(o[2*jp],   pa[t2], vb[0], vb[1]);
                MMA16816(o[2*jp+1], pa[t2], vb[2], vb[3]);
                LDSM4T(vb, sb + AT_VL + off);
                MMA16816(o[2*jp],   pa[t2], vb[0], vb[1]);
                MMA16816(o[2*jp+1], pa[t2], vb[2], vb[3]);
            }
        }
    }

    // write partials (unnormalized, log2-domain stats)
    int r0 = wid*16 + (lane >> 2), r1 = r0 + 8;
    int base = (qb*AKS + sp)*128;
    if ((lane & 3) == 0) {
        g_pm[base + r0] = m0; g_pl[base + r0] = l0;
        g_pm[base + r1] = m1; g_pl[base + r1] = l1;
    }
    int cb = (lane & 3)*2;
    #pragma unroll
    for (int j = 0; j < 16; j++) {
        *(float2*)&g_pacc[((size_t)(base + r0))*128 + 8*j + cb] = make_float2(o[j][0], o[j][1]);
        *(float2*)&g_pacc[((size_t)(base + r1))*128 + 8*j + cb] = make_float2(o[j][2], o[j][3]);
    }
}

// ---------------- combine + column sum --------------------------------------
__global__ __launch_bounds__(256) void combine_kernel() {
    __shared__ float colsum[128];
    int tid = threadIdx.x;
    if (tid < 128) colsum[tid] = 0.f;
    __syncthreads();
    int w = tid >> 5, lane = tid & 31;
    int row0 = blockIdx.x * 32 + w * 4;
    float o0 = 0.f, o1 = 0.f, o2 = 0.f, o3 = 0.f;
    for (int ii = 0; ii < 4; ii++) {
        int r = row0 + ii;
        if (r >= NN) break;
        int qb = r >> 7, rr = r & 127, pb = qb * AKS;
        float mv[AKS], lv[AKS];
        float M = -1e30f;
        #pragma unroll
        for (int c = 0; c < AKS; c++) {
            mv[c] = g_pm[(pb + c)*128 + rr];
            lv[c] = g_pl[(pb + c)*128 + rr];
            M = fmaxf(M, mv[c]);
        }
        float L = 0.f;
        #pragma unroll
        for (int c = 0; c < AKS; c++) L += lv[c] * ex2(mv[c] - M);
        float inv = 1.f / L;
        #pragma unroll
        for (int c = 0; c < AKS; c++) {
            float wg = ex2(mv[c] - M) * inv;
            float4 a = *(const float4*)&g_pacc[((size_t)(pb + c)*128 + rr)*128 + lane*4];
            o0 += wg*a.x; o1 += wg*a.y; o2 += wg*a.z; o3 += wg*a.w;
        }
    }
    atomicAdd(&colsum[lane*4 + 0], o0);
    atomicAdd(&colsum[lane*4 + 1], o1);
    atomicAdd(&colsum[lane*4 + 2], o2);
    atomicAdd(&colsum[lane*4 + 3], o3);
    __syncthreads();
    if (tid < 128) atomicAdd(&g_attnsum[tid], colsum[tid]);
}

__global__ void final_kernel(const float* __restrict__ Wo, const float* __restrict__ bo,
        const float* __restrict__ W1, const float* __restrict__ c1,
        const float* __restrict__ W2, const float* __restrict__ c2,
        const float* __restrict__ W3, const float* __restrict__ c3,
        float* __restrict__ out) {
    __shared__ float st[128];
    __shared__ float x1[64];
    __shared__ float x2[32];
    __shared__ float red[128];
    int t = threadIdx.x;
    const float invN = 1.0f / (float)NN;
    float s = bo[t];
    for (int a = 0; a < 128; a++) s += g_attnsum[a] * invN * Wo[a*128 + t];
    st[t] = s;
    __syncthreads();
    if (t < 64) {
        float v = c1[t];
        for (int a = 0; a < 128; a++) v += st[a] * W1[a*64 + t];
        x1[t] = fmaxf(v, 0.f);
    }
    __syncthreads();
    if (t < 32) {
        float v = c2[t];
        for (int a = 0; a < 64; a++) v += x1[a] * W2[a*32 + t];
        x2[t] = fmaxf(v, 0.f);
    }
    __syncthreads();
    float v3 = c3[t];
    for (int a = 0; a < 32; a++) v3 += x2[a] * W3[a*128 + t];
    red[t] = v3;
    __syncthreads();
    for (int o = 64; o >= 1; o >>= 1) {
        if (t < o) red[t] = fmaxf(red[t], red[t + o]);
        __syncthreads();
    }
    float mx = red[0];
    __syncthreads();
    float e = expf(v3 - mx);
    red[t] = e;
    __syncthreads();
    for (int o = 64; o >= 1; o >>= 1) {
        if (t < o) red[t] += red[t + o];
        __syncthreads();
    }
    out[t] = e / red[0];
}

extern "C" void kernel_launch(void* const* d_in, const int* in_sizes, int n_in,
                              void* d_out, int out_size) {
    const float* nf      = (const float*)d_in[0];
    const float* gi      = (const float*)d_in[1];
    const int*   ei      = (const int*)  d_in[2];
    const float* W1_root = (const float*)d_in[3];
    const float* W1_rel  = (const float*)d_in[4];
    const float* b1      = (const float*)d_in[5];
    const float* W2_root = (const float*)d_in[6];
    const float* W2_rel  = (const float*)d_in[7];
    const float* b2      = (const float*)d_in[8];
    const float* WQ      = (const float*)d_in[9];
    const float* bQ      = (const float*)d_in[10];
    const float* WK      = (const float*)d_in[11];
    const float* bK      = (const float*)d_in[12];
    const float* WV      = (const float*)d_in[13];
    const float* bV      = (const float*)d_in[14];
    const float* WQg     = (const float*)d_in[15];
    const float* bQg     = (const float*)d_in[16];
    const float* WKg     = (const float*)d_in[17];
    const float* bKg     = (const float*)d_in[18];
    const float* WVg     = (const float*)d_in[19];
    const float* bVg     = (const float*)d_in[20];
    const float* Wo      = (const float*)d_in[21];
    const float* bo      = (const float*)d_in[22];
    const float* Wfc1    = (const float*)d_in[23];
    const float* bfc1    = (const float*)d_in[24];
    const float* Wfc2    = (const float*)d_in[25];
    const float* bfc2    = (const float*)d_in[26];
    const float* Wfc3    = (const float*)d_in[27];
    const float* bfc3    = (const float*)d_in[28];
    float* out = (float*)d_out;

    cudaFuncSetAttribute(conv_kernel<true>,  cudaFuncAttributeMaxDynamicSharedMemorySize, CONV_SMEM);
    cudaFuncSetAttribute(conv_kernel<false>, cudaFuncAttributeMaxDynamicSharedMemorySize, CONV_SMEM);
    cudaFuncSetAttribute(qkv_kernel,         cudaFuncAttributeMaxDynamicSharedMemorySize, QKV_SMEM);
    cudaFuncSetAttribute(attn_kernel,        cudaFuncAttributeMaxDynamicSharedMemorySize, AT_SMEM);

    float* agg1;  cudaGetSymbolAddress((void**)&agg1,  g_agg1);
    float* agg2;  cudaGetSymbolAddress((void**)&agg2,  g_agg2);
    float* h;     cudaGetSymbolAddress((void**)&h,     g_h);
    float* embed; cudaGetSymbolAddress((void**)&embed, g_embed);

    const int* src = ei;
    const int* dst = ei + EE;

    zero_kernel<<<(NN*DD + 255)/256, 256>>>();
    scatter_kernel<<<(EE*32)/256, 256>>>(nf, src, dst, agg1);
    conv_kernel<true><<<(NN+31)/32, 256, CONV_SMEM>>>(nf, agg1, W1_root, W1_rel, b1, h);
    scatter_kernel<<<(EE*32)/256, 256>>>(h, src, dst, agg2);
    conv_kernel<false><<<(NN+31)/32, 256, CONV_SMEM>>>(h, agg2, W2_root, W2_rel, b2, embed);
    gbias_kernel<<<1, 384>>>(gi, WQg, bQg, WKg, bKg, WVg, bVg, bQ, bK, bV);
    qkv_kernel<<<(NN+31)/32, 256, QKV_SMEM>>>(WQ, WK, WV);
    attn_kernel<<<dim3(AQB, AKS), 256, AT_SMEM>>>();
    combine_kernel<<<(NN+31)/32, 256>>>();
    final_kernel<<<1, 128>>>(Wo, bo, Wfc1, bfc1, Wfc2, bfc2, Wfc3, bfc3, out);
}

// round 7
// speedup vs baseline: 3.7986x; 1.3208x over previous
#include <cuda_runtime.h>
#include <cuda_bf16.h>
#include <math.h>
#include <stdint.h>

#define NN 10000
#define EE 160000
#define DD 128
#define AQB 79
#define AKS 13

extern __shared__ char smem_raw[];

// attn smem layout (bytes): Q 64KB, then 2 buffers x (KH,KL,VH) 16KB each
#define AT_QH 0
#define AT_QL 32768
#define AT_BUF 65536
#define AT_BUFSZ 49152
#define AT_SMEM (AT_BUF + 2*AT_BUFSZ)

__device__ __forceinline__ uint32_t smem_u32(const void* p) {
    uint32_t a; asm("{ .reg .u64 t; cvta.to.shared.u64 t, %1; cvt.u32.u64 %0, t; }":"=r"(a):"l"(p)); return a;
}
__device__ __forceinline__ float ex2(float x){ float y; asm("ex2.approx.ftz.f32 %0, %1;":"=f"(y):"f"(x)); return y; }

// fast 2^f on the FMA pipe (f <= 0); ~6e-5 rel err, clamped at 2^-120
__device__ __forceinline__ float exp2p(float f) {
    f = fmaxf(f, -120.f);
    float n = rintf(f);
    float r = f - n;
    float p = 0.00961812911f;
    p = fmaf(p, r, 0.05550410866f);
    p = fmaf(p, r, 0.24022650696f);
    p = fmaf(p, r, 0.69314718056f);
    p = fmaf(p, r, 1.0f);
    return p * __int_as_float(((int)n + 127) << 23);
}

#define LDSM4(R, A) asm volatile("ldmatrix.sync.aligned.m8n8.x4.shared.b16 {%0,%1,%2,%3}, [%4];" \
    : "=r"((R)[0]),"=r"((R)[1]),"=r"((R)[2]),"=r"((R)[3]) : "r"(A))
#define LDSM4T(R, A) asm volatile("ldmatrix.sync.aligned.m8n8.x4.trans.shared.b16 {%0,%1,%2,%3}, [%4];" \
    : "=r"((R)[0]),"=r"((R)[1]),"=r"((R)[2]),"=r"((R)[3]) : "r"(A))
#define MMA16816(D, A, B0, B1) asm volatile( \
    "mma.sync.aligned.m16n8k16.row.col.f32.bf16.bf16.f32 {%0,%1,%2,%3}, {%4,%5,%6,%7}, {%8,%9}, {%0,%1,%2,%3};" \
    : "+f"((D)[0]),"+f"((D)[1]),"+f"((D)[2]),"+f"((D)[3]) \
    : "r"((A)[0]),"r"((A)[1]),"r"((A)[2]),"r"((A)[3]), "r"(B0),"r"(B1))
#define CPA(dst, src, ssz) asm volatile("cp.async.ca.shared.global [%0], [%1], 16, %2;" \
    :: "r"(dst), "l"(src), "r"(ssz) : "memory")
#define CPC() asm volatile("cp.async.commit_group;" ::: "memory")
#define CPW(n) asm volatile("cp.async.wait_group %0;" :: "n"(n) : "memory")
#define REDV4(p, v) asm volatile("red.global.add.v4.f32 [%0], {%1,%2,%3,%4};" \
    :: "l"(p), "f"((v).x), "f"((v).y), "f"((v).z), "f"((v).w) : "memory")

// ---------------- scratch ----------------
__device__ float g_agg1[NN*DD];
__device__ float g_agg2[NN*DD];
__device__ float g_h[NN*DD];
__device__ float g_embed[NN*DD];
__device__ __nv_bfloat16 g_Qh[NN*DD], g_Ql[NN*DD], g_Kh[NN*DD], g_Kl[NN*DD];
__device__ __nv_bfloat16 g_Vh[NN*DD];
__device__ float g_gb[3*DD];
__device__ float g_attnsum[DD];
__device__ float g_pm[AQB*AKS*128];
__device__ float g_pl[AQB*AKS*128];
__device__ float g_pacc[(size_t)AQB*AKS*128*128];

__global__ void zero_kernel() {
    int t = blockIdx.x * blockDim.x + threadIdx.x;
    if (t < NN*DD) { g_agg1[t] = 0.f; g_agg2[t] = 0.f; }
    if (t < DD) g_attnsum[t] = 0.f;
}

__global__ __launch_bounds__(256) void scatter_kernel(
        const float* __restrict__ x, const int* __restrict__ src,
        const int* __restrict__ dst, float* __restrict__ agg) {
    int t = blockIdx.x * 256 + threadIdx.x;
    int e = t >> 5;
    if (e >= EE) return;
    int fq = (t & 31) << 2;
    int s = __ldg(src + e), d = __ldg(dst + e);
    float4 v = *reinterpret_cast<const float4*>(x + (size_t)s * DD + fq);
    float* p = agg + (size_t)d * DD + fq;
    REDV4(p, v);
}

#define CONV_SMEM ((256*128 + 32*256) * 4)
template<bool RELU>
__global__ __launch_bounds__(256) void conv_kernel(
        const float* __restrict__ X, const float* __restrict__ Y,
        const float* __restrict__ Wa, const float* __restrict__ Wb,
        const float* __restrict__ bias, float* __restrict__ out) {
    float* sm = (float*)smem_raw;
    float* sW = sm;
    float* sA = sm + 256*128;
    int tid = threadIdx.x;
    int row0 = blockIdx.x * 32;
    for (int i = tid*4; i < 256*128; i += 1024) {
        float4 v;
        if (i < 128*128) v = *reinterpret_cast<const float4*>(Wa + i);
        else             v = *reinterpret_cast<const float4*>(Wb + (i - 128*128));
        *reinterpret_cast<float4*>(sW + i) = v;
    }
    for (int i = tid*4; i < 32*256; i += 1024) {
        int r = i >> 8, c = i & 255;
        int gr = row0 + r;
        float4 v = make_float4(0.f,0.f,0.f,0.f);
        if (gr < NN) {
            if (c < 128) v = *reinterpret_cast<const float4*>(X + (size_t)gr*128 + c);
            else         v = *reinterpret_cast<const float4*>(Y + (size_t)gr*128 + (c-128));
        }
        *reinterpret_cast<float4*>(sA + i) = v;
    }
    __syncthreads();
    int w = tid >> 5, lane = tid & 31;
    int r0 = w * 4;
    float4 bb = *reinterpret_cast<const float4*>(bias + lane*4);
    float acc[4][4];
    #pragma unroll
    for (int i = 0; i < 4; i++) { acc[i][0]=bb.x; acc[i][1]=bb.y; acc[i][2]=bb.z; acc[i][3]=bb.w; }
    for (int k = 0; k < 256; k += 4) {
        float a0[4], a1[4], a2[4], a3[4];
        #pragma unroll
        for (int i = 0; i < 4; i++) {
            float4 t = *reinterpret_cast<const float4*>(sA + (r0+i)*256 + k);
            a0[i]=t.x; a1[i]=t.y; a2[i]=t.z; a3[i]=t.w;
        }
        float4 b;
        b = *reinterpret_cast<const float4*>(sW + (k+0)*128 + lane*4);
        #pragma unroll
        for (int i=0;i<4;i++){ acc[i][0]+=a0[i]*b.x; acc[i][1]+=a0[i]*b.y; acc[i][2]+=a0[i]*b.z; acc[i][3]+=a0[i]*b.w; }
        b = *reinterpret_cast<const float4*>(sW + (k+1)*128 + lane*4);
        #pragma unroll
        for (int i=0;i<4;i++){ acc[i][0]+=a1[i]*b.x; acc[i][1]+=a1[i]*b.y; acc[i][2]+=a1[i]*b.z; acc[i][3]+=a1[i]*b.w; }
        b = *reinterpret_cast<const float4*>(sW + (k+2)*128 + lane*4);
        #pragma unroll
        for (int i=0;i<4;i++){ acc[i][0]+=a2[i]*b.x; acc[i][1]+=a2[i]*b.y; acc[i][2]+=a2[i]*b.z; acc[i][3]+=a2[i]*b.w; }
        b = *reinterpret_cast<const float4*>(sW + (k+3)*128 + lane*4);
        #pragma unroll
        for (int i=0;i<4;i++){ acc[i][0]+=a3[i]*b.x; acc[i][1]+=a3[i]*b.y; acc[i][2]+=a3[i]*b.z; acc[i][3]+=a3[i]*b.w; }
    }
    #pragma unroll
    for (int i = 0; i < 4; i++) {
        int gr = row0 + r0 + i;
        if (gr < NN) {
            float4 o;
            if (RELU) { o.x=fmaxf(acc[i][0],0.f); o.y=fmaxf(acc[i][1],0.f); o.z=fmaxf(acc[i][2],0.f); o.w=fmaxf(acc[i][3],0.f); }
            else      { o.x=acc[i][0]; o.y=acc[i][1]; o.z=acc[i][2]; o.w=acc[i][3]; }
            *reinterpret_cast<float4*>(out + (size_t)gr*128 + lane*4) = o;
        }
    }
}

__global__ void gbias_kernel(const float* __restrict__ g,
        const float* __restrict__ WQg, const float* __restrict__ bQg,
        const float* __restrict__ WKg, const float* __restrict__ bKg,
        const float* __restrict__ WVg, const float* __restrict__ bVg,
        const float* __restrict__ bQ, const float* __restrict__ bK,
        const float* __restrict__ bV) {
    int t = threadIdx.x;
    int m = t >> 7, f = t & 127;
    const float* Wg = (m == 0) ? WQg : ((m == 1) ? WKg : WVg);
    const float* bg = (m == 0) ? bQg : ((m == 1) ? bKg : bVg);
    const float* bn = (m == 0) ? bQ  : ((m == 1) ? bK  : bV);
    float s = bg[f] + bn[f];
    for (int d = 0; d < 64; d++) s += g[d] * Wg[d*128 + f];
    g_gb[t] = s;
}

__device__ __forceinline__ void cvt4(const float* a, uint2& hh, uint2& ll) {
    __nv_bfloat16 h0=__float2bfloat16_rn(a[0]), h1=__float2bfloat16_rn(a[1]);
    __nv_bfloat16 h2=__float2bfloat16_rn(a[2]), h3=__float2bfloat16_rn(a[3]);
    __nv_bfloat16 l0=__float2bfloat16_rn(a[0]-__bfloat162float(h0));
    __nv_bfloat16 l1=__float2bfloat16_rn(a[1]-__bfloat162float(h1));
    __nv_bfloat16 l2=__float2bfloat16_rn(a[2]-__bfloat162float(h2));
    __nv_bfloat16 l3=__float2bfloat16_rn(a[3]-__bfloat162float(h3));
    __nv_bfloat162 H0{h0,h1}, H1{h2,h3}, L0{l0,l1}, L1{l2,l3};
    hh = make_uint2(*(uint32_t*)&H0, *(uint32_t*)&H1);
    ll = make_uint2(*(uint32_t*)&L0, *(uint32_t*)&L1);
}

#define QKV_SMEM ((128*384 + 32*128) * 4)
__global__ __launch_bounds__(256) void qkv_kernel(
        const float* __restrict__ WQ, const float* __restrict__ WK,
        const float* __restrict__ WV) {
    float* sm = (float*)smem_raw;
    float* sW = sm;
    float* sA = sm + 128*384;
    int tid = threadIdx.x;
    int row0 = blockIdx.x * 32;
    const float CQ = 0.08838834764831845f * 1.4426950408889634f;  // 1/sqrt(128)*log2(e)
    for (int i = tid*4; i < 128*384; i += 1024) {
        int k = i / 384, c = i % 384;
        int m = c >> 7, cc = c & 127;
        const float* W = (m == 0) ? WQ : ((m == 1) ? WK : WV);
        *reinterpret_cast<float4*>(sW + i) = *reinterpret_cast<const float4*>(W + k*128 + cc);
    }
    for (int i = tid*4; i < 32*128; i += 1024) {
        int r = i >> 7, c = i & 127;
        int gr = row0 + r;
        float4 v = make_float4(0.f,0.f,0.f,0.f);
        if (gr < NN) v = *reinterpret_cast<const float4*>(g_embed + (size_t)gr*128 + c);
        *reinterpret_cast<float4*>(sA + i) = v;
    }
    __syncthreads();
    int w = tid >> 5, lane = tid & 31;
    int r0 = w * 4;
    float acc[4][12];
    {
        float4 q0 = *reinterpret_cast<const float4*>(g_gb + 0*128 + lane*4);
        float4 q1 = *reinterpret_cast<const float4*>(g_gb + 1*128 + lane*4);
        float4 q2 = *reinterpret_cast<const float4*>(g_gb + 2*128 + lane*4);
        #pragma unroll
        for (int i = 0; i < 4; i++) {
            acc[i][0]=q0.x; acc[i][1]=q0.y; acc[i][2]=q0.z; acc[i][3]=q0.w;
            acc[i][4]=q1.x; acc[i][5]=q1.y; acc[i][6]=q1.z; acc[i][7]=q1.w;
            acc[i][8]=q2.x; acc[i][9]=q2.y; acc[i][10]=q2.z; acc[i][11]=q2.w;
        }
    }
    for (int k = 0; k < 128; k++) {
        float4 b0 = *reinterpret_cast<const float4*>(sW + k*384 +   0 + lane*4);
        float4 b1 = *reinterpret_cast<const float4*>(sW + k*384 + 128 + lane*4);
        float4 b2 = *reinterpret_cast<const float4*>(sW + k*384 + 256 + lane*4);
        #pragma unroll
        for (int i = 0; i < 4; i++) {
            float a = sA[(r0+i)*128 + k];
            acc[i][0]+=a*b0.x; acc[i][1]+=a*b0.y; acc[i][2]+=a*b0.z;  acc[i][3]+=a*b0.w;
            acc[i][4]+=a*b1.x; acc[i][5]+=a*b1.y; acc[i][6]+=a*b1.z;  acc[i][7]+=a*b1.w;
            acc[i][8]+=a*b2.x; acc[i][9]+=a*b2.y; acc[i][10]+=a*b2.z; acc[i][11]+=a*b2.w;
        }
    }
    #pragma unroll
    for (int i = 0; i < 4; i++) {
        int gr = row0 + r0 + i;
        if (gr < NN) {
            uint2 hh, ll;
            float qs[4] = {acc[i][0]*CQ, acc[i][1]*CQ, acc[i][2]*CQ, acc[i][3]*CQ};
            cvt4(qs, hh, ll);
            *(uint2*)&g_Qh[(size_t)gr*128 + lane*4] = hh;
            *(uint2*)&g_Ql[(size_t)gr*128 + lane*4] = ll;
            cvt4(&acc[i][4], hh, ll);
            *(uint2*)&g_Kh[(size_t)gr*128 + lane*4] = hh;
            *(uint2*)&g_Kl[(size_t)gr*128 + lane*4] = ll;
            __nv_bfloat162 v0 = __floats2bfloat162_rn(acc[i][8], acc[i][9]);
            __nv_bfloat162 v1 = __floats2bfloat162_rn(acc[i][10], acc[i][11]);
            *(uint2*)&g_Vh[(size_t)gr*128 + lane*4] =
                make_uint2(*(uint32_t*)&v0, *(uint32_t*)&v1);
        }
    }
}

// ---------------- mma.sync flash attention (cp.async double-buffered) ------
__global__ __launch_bounds__(256, 1) void attn_kernel() {
    char* sm = smem_raw;
    uint32_t sb = smem_u32(sm);
    const int tid = threadIdx.x, wid = tid >> 5, lane = tid & 31;
    const int qb = blockIdx.x, sp = blockIdx.y;
    const int q0 = qb * 128;
    const int kbeg = sp * 768;
    const int kend = (sp == AKS-1) ? NN : kbeg + 768;
    const int nch = (kend - kbeg + 63) >> 6;

    // stage Q hi/lo (swizzled 16B chunks)
    for (int t = tid; t < 2048; t += 256) {
        int r = t >> 4, c = t & 15;
        int gr = q0 + r;
        uint4 vh = make_uint4(0,0,0,0), vl = make_uint4(0,0,0,0);
        if (gr < NN) {
            vh = *(const uint4*)&g_Qh[(size_t)gr*128 + c*8];
            vl = *(const uint4*)&g_Ql[(size_t)gr*128 + c*8];
        }
        uint32_t off = (uint32_t)(r*256 + ((c ^ (r & 7)) << 4));
        *(uint4*)(sm + AT_QH + off) = vh;
        *(uint4*)(sm + AT_QL + off) = vl;
    }

    // prefetch chunk 0 into buffer 0
    {
        int kt = kbeg;
        int kn = min(64, kend - kt);
        uint32_t base = sb + AT_BUF;
        for (int t = tid; t < 1024; t += 256) {
            int r = t >> 4, c = t & 15;
            int rr = (r < kn) ? r : 0;
            uint32_t ssz = (r < kn) ? 16u : 0u;
            size_t go = (size_t)(kt + rr)*128 + c*8;
            uint32_t off = (uint32_t)(r*256 + ((c ^ (r & 7)) << 4));
            CPA(base + off,         &g_Kh[go], ssz);
            CPA(base + 16384 + off, &g_Kl[go], ssz);
            CPA(base + 32768 + off, &g_Vh[go], ssz);
        }
        CPC();
    }
    __syncthreads();

    const int g8 = lane >> 3, i8 = lane & 7;
    uint32_t qh[8][4], ql[8][4];
    {
        int row = wid*16 + i8 + ((g8 & 1) << 3);
        #pragma unroll
        for (int t = 0; t < 8; t++) {
            uint32_t ch = (uint32_t)((2*t + (g8 >> 1)) ^ (row & 7));
            uint32_t off = (uint32_t)(row*256) + (ch << 4);
            LDSM4(qh[t], sb + AT_QH + off);
            LDSM4(ql[t], sb + AT_QL + off);
        }
    }

    float m0 = -1e30f, m1 = -1e30f, l0 = 0.f, l1 = 0.f;
    float o[16][4];
    #pragma unroll
    for (int j = 0; j < 16; j++) { o[j][0]=0.f; o[j][1]=0.f; o[j][2]=0.f; o[j][3]=0.f; }

    for (int ic = 0; ic < nch; ic++) {
        const int kt = kbeg + ic*64;
        const int kn = min(64, kend - kt);
        __syncthreads();   // prior compute done before refilling next buffer
        if (ic + 1 < nch) {
            int kt2 = kt + 64;
            int kn2 = min(64, kend - kt2);
            uint32_t base = sb + AT_BUF + ((ic + 1) & 1) * AT_BUFSZ;
            for (int t = tid; t < 1024; t += 256) {
                int r = t >> 4, c = t & 15;
                int rr = (r < kn2) ? r : 0;
                uint32_t ssz = (r < kn2) ? 16u : 0u;
                size_t go = (size_t)(kt2 + rr)*128 + c*8;
                uint32_t off = (uint32_t)(r*256 + ((c ^ (r & 7)) << 4));
                CPA(base + off,         &g_Kh[go], ssz);
                CPA(base + 16384 + off, &g_Kl[go], ssz);
                CPA(base + 32768 + off, &g_Vh[go], ssz);
            }
            CPC();
            CPW(1);
        } else {
            CPW(0);
        }
        __syncthreads();
        const uint32_t kbase = sb + AT_BUF + (ic & 1) * AT_BUFSZ;

        // S = Qh*Kh + Qh*Kl + Ql*Kh   (16x64 per warp)
        float s[8][4];
        #pragma unroll
        for (int j = 0; j < 8; j++) { s[j][0]=0.f; s[j][1]=0.f; s[j][2]=0.f; s[j][3]=0.f; }
        #pragma unroll
        for (int t = 0; t < 8; t++) {
            #pragma unroll
            for (int jp = 0; jp < 4; jp++) {
                int row = 16*jp + i8 + ((g8 >> 1) << 3);
                uint32_t ch = (uint32_t)((2*t + (g8 & 1)) ^ (row & 7));
                uint32_t off = (uint32_t)(row*256) + (ch << 4);
                uint32_t kb[4];
                LDSM4(kb, kbase + off);
                MMA16816(s[2*jp],   qh[t], kb[0], kb[1]);
                MMA16816(s[2*jp+1], qh[t], kb[2], kb[3]);
                MMA16816(s[2*jp],   ql[t], kb[0], kb[1]);
                MMA16816(s[2*jp+1], ql[t], kb[2], kb[3]);
                LDSM4(kb, kbase + 16384 + off);
                MMA16816(s[2*jp],   qh[t], kb[0], kb[1]);
                MMA16816(s[2*jp+1], qh[t], kb[2], kb[3]);
            }
        }

        if (kn < 64) {
            int cb = (lane & 3)*2;
            #pragma unroll
            for (int j = 0; j < 8; j++)
                if (8*j + cb >= kn) { s[j][0]=-1e30f; s[j][1]=-1e30f; s[j][2]=-1e30f; s[j][3]=-1e30f; }
        }

        float rm0 = -1e30f, rm1 = -1e30f;
        #pragma unroll
        for (int j = 0; j < 8; j++) {
            rm0 = fmaxf(rm0, fmaxf(s[j][0], s[j][1]));
            rm1 = fmaxf(rm1, fmaxf(s[j][2], s[j][3]));
        }
        rm0 = fmaxf(rm0, __shfl_xor_sync(0xffffffffu, rm0, 1));
        rm0 = fmaxf(rm0, __shfl_xor_sync(0xffffffffu, rm0, 2));
        rm1 = fmaxf(rm1, __shfl_xor_sync(0xffffffffu, rm1, 1));
        rm1 = fmaxf(rm1, __shfl_xor_sync(0xffffffffu, rm1, 2));
        float mn0 = fmaxf(m0, rm0), mn1 = fmaxf(m1, rm1);
        float a0 = exp2p(m0 - mn0), a1 = exp2p(m1 - mn1);
        m0 = mn0; m1 = mn1;

        float sum0 = 0.f, sum1 = 0.f;
        #pragma unroll
        for (int j = 0; j < 8; j++) {
            s[j][0] = exp2p(s[j][0] - mn0); s[j][1] = exp2p(s[j][1] - mn0);
            s[j][2] = exp2p(s[j][2] - mn1); s[j][3] = exp2p(s[j][3] - mn1);
            sum0 += s[j][0] + s[j][1]; sum1 += s[j][2] + s[j][3];
        }
        sum0 += __shfl_xor_sync(0xffffffffu, sum0, 1);
        sum0 += __shfl_xor_sync(0xffffffffu, sum0, 2);
        sum1 += __shfl_xor_sync(0xffffffffu, sum1, 1);
        sum1 += __shfl_xor_sync(0xffffffffu, sum1, 2);
        l0 = l0*a0 + sum0; l1 = l1*a1 + sum1;

        uint32_t pa[4][4];
        #pragma unroll
        for (int t2 = 0; t2 < 4; t2++) {
            __nv_bfloat162 b;
            b = __floats2bfloat162_rn(s[2*t2][0],   s[2*t2][1]);   pa[t2][0] = *(uint32_t*)&b;
            b = __floats2bfloat162_rn(s[2*t2][2],   s[2*t2][3]);   pa[t2][1] = *(uint32_t*)&b;
            b = __floats2bfloat162_rn(s[2*t2+1][0], s[2*t2+1][1]); pa[t2][2] = *(uint32_t*)&b;
            b = __floats2bfloat162_rn(s[2*t2+1][2], s[2*t2+1][3]); pa[t2][3] = *(uint32_t*)&b;
        }

        if (!__all_sync(0xffffffffu, (a0 == 1.f) && (a1 == 1.f))) {
            #pragma unroll
            for (int j = 0; j < 16; j++) {
                o[j][0]*=a0; o[j][1]*=a0; o[j][2]*=a1; o[j][3]*=a1;
            }
        }

        // O += P @ Vh
        #pragma unroll
        for (int t2 = 0; t2 < 4; t2++) {
            #pragma unroll
            for (int jp = 0; jp < 8; jp++) {
                int row = 16*t2 + i8 + ((g8 & 1) << 3);
                uint32_t ch = (uint32_t)((2*jp + (g8 >> 1)) ^ (row & 7));
                uint32_t off = (uint32_t)(row*256) + (ch << 4);
                uint32_t vb[4];
                LDSM4T(vb, kbase + 32768 + off);
                MMA16816(o[2*jp],   pa[t2], vb[0], vb[1]);
                MMA16816(o[2*jp+1], pa[t2], vb[2], vb[3]);
            }
        }
    }

    // write partials (unnormalized, log2-domain stats)
    int r0 = wid*16 + (lane >> 2), r1 = r0 + 8;
    int base = (qb*AKS + sp)*128;
    if ((lane & 3) == 0) {
        g_pm[base + r0] = m0; g_pl[base + r0] = l0;
        g_pm[base + r1] = m1; g_pl[base + r1] = l1;
    }
    int cb = (lane & 3)*2;
    #pragma unroll
    for (int j = 0; j < 16; j++) {
        *(float2*)&g_pacc[((size_t)(base + r0))*128 + 8*j + cb] = make_float2(o[j][0], o[j][1]);
        *(float2*)&g_pacc[((size_t)(base + r1))*128 + 8*j + cb] = make_float2(o[j][2], o[j][3]);
    }
}

// ---------------- combine + column sum --------------------------------------
__global__ __launch_bounds__(256) void combine_kernel() {
    __shared__ float colsum[128];
    int tid = threadIdx.x;
    if (tid < 128) colsum[tid] = 0.f;
    __syncthreads();
    int w = tid >> 5, lane = tid & 31;
    int row0 = blockIdx.x * 32 + w * 4;
    float o0 = 0.f, o1 = 0.f, o2 = 0.f, o3 = 0.f;
    for (int ii = 0; ii < 4; ii++) {
        int r = row0 + ii;
        if (r >= NN) break;
        int qb = r >> 7, rr = r & 127, pb = qb * AKS;
        float mv[AKS], lv[AKS];
        float M = -1e30f;
        #pragma unroll
        for (int c = 0; c < AKS; c++) {
            mv[c] = g_pm[(pb + c)*128 + rr];
            lv[c] = g_pl[(pb + c)*128 + rr];
            M = fmaxf(M, mv[c]);
        }
        float L = 0.f;
        #pragma unroll
        for (int c = 0; c < AKS; c++) L += lv[c] * ex2(mv[c] - M);
        float inv = 1.f / L;
        #pragma unroll
        for (int c = 0; c < AKS; c++) {
            float wg = ex2(mv[c] - M) * inv;
            float4 a = *(const float4*)&g_pacc[((size_t)(pb + c)*128 + rr)*128 + lane*4];
            o0 += wg*a.x; o1 += wg*a.y; o2 += wg*a.z; o3 += wg*a.w;
        }
    }
    atomicAdd(&colsum[lane*4 + 0], o0);
    atomicAdd(&colsum[lane*4 + 1], o1);
    atomicAdd(&colsum[lane*4 + 2], o2);
    atomicAdd(&colsum[lane*4 + 3], o3);
    __syncthreads();
    if (tid < 128) atomicAdd(&g_attnsum[tid], colsum[tid]);
}

__global__ void final_kernel(const float* __restrict__ Wo, const float* __restrict__ bo,
        const float* __restrict__ W1, const float* __restrict__ c1,
        const float* __restrict__ W2, const float* __restrict__ c2,
        const float* __restrict__ W3, const float* __restrict__ c3,
        float* __restrict__ out) {
    __shared__ float st[128];
    __shared__ float x1[64];
    __shared__ float x2[32];
    __shared__ float red[128];
    int t = threadIdx.x;
    const float invN = 1.0f / (float)NN;
    float s = bo[t];
    for (int a = 0; a < 128; a++) s += g_attnsum[a] * invN * Wo[a*128 + t];
    st[t] = s;
    __syncthreads();
    if (t < 64) {
        float v = c1[t];
        for (int a = 0; a < 128; a++) v += st[a] * W1[a*64 + t];
        x1[t] = fmaxf(v, 0.f);
    }
    __syncthreads();
    if (t < 32) {
        float v = c2[t];
        for (int a = 0; a < 64; a++) v += x1[a] * W2[a*32 + t];
        x2[t] = fmaxf(v, 0.f);
    }
    __syncthreads();
    float v3 = c3[t];
    for (int a = 0; a < 32; a++) v3 += x2[a] * W3[a*128 + t];
    red[t] = v3;
    __syncthreads();
    for (int o = 64; o >= 1; o >>= 1) {
        if (t < o) red[t] = fmaxf(red[t], red[t + o]);
        __syncthreads();
    }
    float mx = red[0];
    __syncthreads();
    float e = expf(v3 - mx);
    red[t] = e;
    __syncthreads();
    for (int o = 64; o >= 1; o >>= 1) {
        if (t < o) red[t] += red[t + o];
        __syncthreads();
    }
    out[t] = e / red[0];
}

extern "C" void kernel_launch(void* const* d_in, const int* in_sizes, int n_in,
                              void* d_out, int out_size) {
    const float* nf      = (const float*)d_in[0];
    const float* gi      = (const float*)d_in[1];
    const int*   ei      = (const int*)  d_in[2];
    const float* W1_root = (const float*)d_in[3];
    const float* W1_rel  = (const float*)d_in[4];
    const float* b1      = (const float*)d_in[5];
    const float* W2_root = (const float*)d_in[6];
    const float* W2_rel  = (const float*)d_in[7];
    const float* b2      = (const float*)d_in[8];
    const float* WQ      = (const float*)d_in[9];
    const float* bQ      = (const float*)d_in[10];
    const float* WK      = (const float*)d_in[11];
    const float* bK      = (const float*)d_in[12];
    const float* WV      = (const float*)d_in[13];
    const float* bV      = (const float*)d_in[14];
    const float* WQg     = (const float*)d_in[15];
    const float* bQg     = (const float*)d_in[16];
    const float* WKg     = (const float*)d_in[17];
    const float* bKg     = (const float*)d_in[18];
    const float* WVg     = (const float*)d_in[19];
    const float* bVg     = (const float*)d_in[20];
    const float* Wo      = (const float*)d_in[21];
    const float* bo      = (const float*)d_in[22];
    const float* Wfc1    = (const float*)d_in[23];
    const float* bfc1    = (const float*)d_in[24];
    const float* Wfc2    = (const float*)d_in[25];
    const float* bfc2    = (const float*)d_in[26];
    const float* Wfc3    = (const float*)d_in[27];
    const float* bfc3    = (const float*)d_in[28];
    float* out = (float*)d_out;

    cudaFuncSetAttribute(conv_kernel<true>,  cudaFuncAttributeMaxDynamicSharedMemorySize, CONV_SMEM);
    cudaFuncSetAttribute(conv_kernel<false>, cudaFuncAttributeMaxDynamicSharedMemorySize, CONV_SMEM);
    cudaFuncSetAttribute(qkv_kernel,         cudaFuncAttributeMaxDynamicSharedMemorySize, QKV_SMEM);
    cudaFuncSetAttribute(attn_kernel,        cudaFuncAttributeMaxDynamicSharedMemorySize, AT_SMEM);

    float* agg1;  cudaGetSymbolAddress((void**)&agg1,  g_agg1);
    float* agg2;  cudaGetSymbolAddress((void**)&agg2,  g_agg2);
    float* h;     cudaGetSymbolAddress((void**)&h,     g_h);
    float* embed; cudaGetSymbolAddress((void**)&embed, g_embed);

    const int* src = ei;
    const int* dst = ei + EE;

    zero_kernel<<<(NN*DD + 255)/256, 256>>>();
    scatter_kernel<<<(EE*32)/256, 256>>>(nf, src, dst, agg1);
    conv_kernel<true><<<(NN+31)/32, 256, CONV_SMEM>>>(nf, agg1, W1_root, W1_rel, b1, h);
    scatter_kernel<<<(EE*32)/256, 256>>>(h, src, dst, agg2);
    conv_kernel<false><<<(NN+31)/32, 256, CONV_SMEM>>>(h, agg2, W2_root, W2_rel, b2, embed);
    gbias_kernel<<<1, 384>>>(gi, WQg, bQg, WKg, bKg, WVg, bVg, bQ, bK, bV);
    qkv_kernel<<<(NN+31)/32, 256, QKV_SMEM>>>(WQ, WK, WV);
    attn_kernel<<<dim3(AQB, AKS), 256, AT_SMEM>>>();
    combine_kernel<<<(NN+31)/32, 256>>>();
    final_kernel<<<1, 128>>>(Wo, bo, Wfc1, bfc1, Wfc2, bfc2, Wfc3, bfc3, out);
}